// round 12
// baseline (speedup 1.0000x reference)
#include <cuda_runtime.h>
#include <cstdint>

// ---------------------------------------------------------------------------
// CMPNN, restructured:
//   x_proj = relu(x @ W_atom + b)                         [N,128]
//   loop l=0..2:
//     msg[i] = sum_e m_e * max_e m_e ; h_atom *= msg
//     U = h_atom @ W_l ; V = h_bondN @ W_l                [N,128] each
//     h_bondN[v] = relu(U[iI[v]] - V[iJ[v]] + b_l)  (rows < N only)
//   final msg -> hfin = h_atom^2 * msg
//   out = [hfin | x_proj] @ W_lin + b_lin                 [N,64]
// GEMMs: scalar FFMA, BM=64 tiles, 256 threads x (4x8) accumulators for
// 37.5% occupancy (was reg-bound at 18%), cp.async double-buffered,
// quad-amortized LDS.128 A-fragment loads.
// h_bond [E,128] is never materialized: m_e = relu(U[i_e]-V[j_e]+b).
// ---------------------------------------------------------------------------

#define NN_MAX 30000
#define EE_MAX 480000

__device__ int g_is64;
__device__ int g_idxI[EE_MAX];
__device__ int g_idxJ[EE_MAX];
__device__ int g_deg[NN_MAX];
__device__ int g_rowptr[NN_MAX + 1];
__device__ int g_cursor[NN_MAX];
__device__ int g_sortedJ[EE_MAX];
__device__ int g_sortedE[EE_MAX];

__device__ __align__(16) float g_xproj[NN_MAX * 128];
__device__ __align__(16) float g_hatom[NN_MAX * 128];
__device__ __align__(16) float g_hbondN[NN_MAX * 128];
__device__ __align__(16) float g_U[NN_MAX * 128];
__device__ __align__(16) float g_V[NN_MAX * 128];

// ------------------------------- index setup -------------------------------

__global__ void init_kernel(const int* __restrict__ raw, int e, int n) {
    if (blockIdx.x == 0) {
        __shared__ int nz;
        if (threadIdx.x == 0) nz = 0;
        __syncthreads();
        int K = e < 2048 ? e : 2048;
        for (int t = threadIdx.x; t < K; t += blockDim.x)
            if (raw[2 * t + 1] != 0) nz = 1;
        __syncthreads();
        if (threadIdx.x == 0) g_is64 = (nz == 0) ? 1 : 0;
    }
    int t = blockIdx.x * blockDim.x + threadIdx.x;
    if (t < n) g_deg[t] = 0;
}

__global__ void convert_hist_kernel(const int* __restrict__ raw, int e) {
    int t = blockIdx.x * blockDim.x + threadIdx.x;
    if (t >= e) return;
    int i, j;
    if (g_is64) { i = raw[2 * t]; j = raw[2 * (e + t)]; }
    else        { i = raw[t];     j = raw[e + t]; }
    g_idxI[t] = i;
    g_idxJ[t] = j;
    atomicAdd(&g_deg[i], 1);
}

// Single-block exclusive scan, thread-coarsened + warp shuffles.
__global__ __launch_bounds__(1024) void scan_kernel(int n) {
    const int ITEMS = 32;                 // 1024*32 = 32768 >= NN_MAX
    __shared__ int wsum[32];
    int t = threadIdx.x;
    int base = t * ITEMS;
    int pre[ITEMS];
    int tot = 0;
#pragma unroll
    for (int i = 0; i < ITEMS; i++) {
        int idx = base + i;
        int d = (idx < n) ? g_deg[idx] : 0;
        pre[i] = tot;
        tot += d;
    }
    int lane = t & 31, wid = t >> 5;
    int incl = tot;
#pragma unroll
    for (int o = 1; o < 32; o <<= 1) {
        int v = __shfl_up_sync(0xffffffffu, incl, o);
        if (lane >= o) incl += v;
    }
    if (lane == 31) wsum[wid] = incl;
    __syncthreads();
    if (wid == 0) {
        int v = wsum[lane];
#pragma unroll
        for (int o = 1; o < 32; o <<= 1) {
            int u = __shfl_up_sync(0xffffffffu, v, o);
            if (lane >= o) v += u;
        }
        wsum[lane] = v;
    }
    __syncthreads();
    int warp_off = (wid > 0) ? wsum[wid - 1] : 0;
    int excl = warp_off + incl - tot;
#pragma unroll
    for (int i = 0; i < ITEMS; i++) {
        int idx = base + i;
        if (idx < n) {
            int p = excl + pre[i];
            g_rowptr[idx] = p;
            g_cursor[idx] = p;
        }
    }
    if (t == 1023) g_rowptr[n] = warp_off + incl;
}

__global__ void scatter_kernel(int e) {
    int t = blockIdx.x * blockDim.x + threadIdx.x;
    if (t >= e) return;
    int i = g_idxI[t];
    int p = atomicAdd(&g_cursor[i], 1);
    g_sortedJ[p] = g_idxJ[t];
    g_sortedE[p] = t;
}

// ------------------------------ 64-row SGEMM --------------------------------
// C[M,128] = act(A[M,128] @ W[128,128] + bias), BM=64 per CTA, 256 threads.
// Dual-source: blocks < nblk use (A1,C1), the rest (A2,C2).
// cp.async 2-stage pipeline over BK=32 chunks. Conflict-free smem:
//   A stage [64][32] row-major, quad q of row r stored at q^(r&7);
//   per k-QUAD one LDS.128 per row (broadcast), banks disjoint across the
//   warp's two ty-rows because the XOR swizzle flips quad bit 2.
// Thread (tx=tid&15, ty=tid>>4) owns rows ty*4..+3, cols {4tx..+3, 64+4tx..+3}.

#define G64_STG_A (64 * 32)                 // floats
#define G64_STG_B (32 * 128)                // floats
#define G64_STG   (G64_STG_A + G64_STG_B)   // 6144 floats = 24 KB
#define G64_SMEM  (2 * G64_STG * 4)         // 48 KB

__device__ __forceinline__ uint32_t smem_u32(const void* p) {
    uint32_t a;
    asm("{ .reg .u64 t; cvta.to.shared.u64 t, %1; cvt.u32.u64 %0, t; }"
        : "=r"(a) : "l"(p));
    return a;
}
__device__ __forceinline__ void cp16(uint32_t dst, const void* src) {
    asm volatile("cp.async.ca.shared.global [%0], [%1], 16;"
                 :: "r"(dst), "l"(src));
}

__global__ __launch_bounds__(256, 3) void gemm64_kernel(
    const float* __restrict__ A1, const float* __restrict__ A2,
    const float* __restrict__ W, const float* __restrict__ bias,
    float* __restrict__ C1, float* __restrict__ C2,
    int M, int nblk, int act)
{
    extern __shared__ float sm[];
    uint32_t sbase = smem_u32(sm);

    const float* __restrict__ A;
    float* __restrict__ C;
    int bx = blockIdx.x;
    if (bx < nblk) { A = A1; C = C1; } else { A = A2; C = C2; bx -= nblk; }
    int row0 = bx * 64;
    int tid = threadIdx.x;
    int tx = tid & 15, ty = tid >> 4;

    auto load_chunk = [&](int c, int s) {
        uint32_t aBase = sbase + (uint32_t)(s * G64_STG) * 4u;
        uint32_t bBase = aBase + (uint32_t)G64_STG_A * 4u;
#pragma unroll
        for (int i = 0; i < 2; i++) {           // A: 64x32 fl = 512 f4
            int idx = tid + i * 256;
            int r = idx >> 3, q = idx & 7;
            int gr = row0 + r; if (gr > M - 1) gr = M - 1;   // tail rows discarded
            uint32_t dst = aBase + (uint32_t)(r * 32 + ((q ^ (r & 7)) << 2)) * 4u;
            cp16(dst, A + (size_t)gr * 128 + c * 32 + q * 4);
        }
#pragma unroll
        for (int i = 0; i < 4; i++) {           // B: 32x128 fl = 1024 f4
            int idx = tid + i * 256;
            int k = idx >> 5, q = idx & 31;
            uint32_t dst = bBase + (uint32_t)(k * 128 + q * 4) * 4u;
            cp16(dst, W + (size_t)(c * 32 + k) * 128 + q * 4);
        }
        asm volatile("cp.async.commit_group;");
    };

    float acc[4][8];
#pragma unroll
    for (int i = 0; i < 4; i++)
#pragma unroll
        for (int j = 0; j < 8; j++) acc[i][j] = 0.f;

    load_chunk(0, 0);

    for (int c = 0; c < 4; c++) {
        int s = c & 1;
        if (c < 3) {
            load_chunk(c + 1, s ^ 1);
            asm volatile("cp.async.wait_group 1;");
        } else {
            asm volatile("cp.async.wait_group 0;");
        }
        __syncthreads();
        const float* Asf = sm + s * G64_STG;
        const float* Bsf = Asf + G64_STG_A;
#pragma unroll 2
        for (int kq = 0; kq < 8; kq++) {        // k-quad: 4 k-steps
            float4 a4[4];
#pragma unroll
            for (int i = 0; i < 4; i++) {
                int r = ty * 4 + i;
                a4[i] = *(const float4*)(Asf + r * 32 + ((kq ^ (r & 7)) << 2));
            }
#pragma unroll
            for (int kk = 0; kk < 4; kk++) {
                int k = kq * 4 + kk;
                float4 b0 = *(const float4*)(Bsf + k * 128 + 4 * tx);
                float4 b1 = *(const float4*)(Bsf + k * 128 + 64 + 4 * tx);
                float a[4];
#pragma unroll
                for (int i = 0; i < 4; i++)
                    a[i] = (kk == 0) ? a4[i].x : (kk == 1) ? a4[i].y
                         : (kk == 2) ? a4[i].z : a4[i].w;
#pragma unroll
                for (int i = 0; i < 4; i++) {
                    acc[i][0] = fmaf(a[i], b0.x, acc[i][0]);
                    acc[i][1] = fmaf(a[i], b0.y, acc[i][1]);
                    acc[i][2] = fmaf(a[i], b0.z, acc[i][2]);
                    acc[i][3] = fmaf(a[i], b0.w, acc[i][3]);
                    acc[i][4] = fmaf(a[i], b1.x, acc[i][4]);
                    acc[i][5] = fmaf(a[i], b1.y, acc[i][5]);
                    acc[i][6] = fmaf(a[i], b1.z, acc[i][6]);
                    acc[i][7] = fmaf(a[i], b1.w, acc[i][7]);
                }
            }
        }
        __syncthreads();
    }

    float bb[8];
    if (bias) {
#pragma unroll
        for (int j = 0; j < 4; j++) { bb[j] = bias[4 * tx + j]; bb[4 + j] = bias[64 + 4 * tx + j]; }
    } else {
#pragma unroll
        for (int j = 0; j < 8; j++) bb[j] = 0.f;
    }
#pragma unroll
    for (int i = 0; i < 4; i++) {
        int r = row0 + ty * 4 + i;
        if (r < M) {
            float v[8];
#pragma unroll
            for (int j = 0; j < 8; j++) {
                float t = acc[i][j] + bb[j];
                v[j] = act ? fmaxf(t, 0.f) : t;
            }
            float* op = C + (size_t)r * 128;
            *(float4*)(op + 4 * tx)      = make_float4(v[0], v[1], v[2], v[3]);
            *(float4*)(op + 64 + 4 * tx) = make_float4(v[4], v[5], v[6], v[7]);
        }
    }
}

// -------------------------- out GEMM (BM=64, N=64) ---------------------------
// out[N,64] = [hfin | xproj] @ W_lin[256,64] + b_lin. K=256 in 8 chunks;
// chunks 0-3 read g_hbondN (hfin), 4-7 g_xproj. 128 threads, 8x4 acc.

#define GO_STG_A (64 * 32)
#define GO_STG_B (32 * 64)
#define GO_STG   (GO_STG_A + GO_STG_B)      // 4096 floats = 16 KB
#define GO_SMEM  (2 * GO_STG * 4)           // 32 KB

__global__ __launch_bounds__(128) void gemm_out_kernel(
    const float* __restrict__ Wlin, const float* __restrict__ blin,
    float* __restrict__ out, int M)
{
    extern __shared__ float sm[];
    uint32_t sbase = smem_u32(sm);
    int row0 = blockIdx.x * 64;
    int tid = threadIdx.x;
    int tx = tid & 15, ty = tid >> 4;

    auto load_chunk = [&](int c, int s) {
        const float* Asrc = (c < 4) ? g_hbondN : g_xproj;
        int kb = (c & 3) * 32;
        uint32_t aBase = sbase + (uint32_t)(s * GO_STG) * 4u;
        uint32_t bBase = aBase + (uint32_t)GO_STG_A * 4u;
#pragma unroll
        for (int i = 0; i < 4; i++) {           // A: 64x32 fl = 512 f4
            int idx = tid + i * 128;
            int r = idx >> 3, q = idx & 7;
            int gr = row0 + r; if (gr > M - 1) gr = M - 1;
            uint32_t dst = aBase + (uint32_t)(r * 32 + ((q ^ (r & 7)) << 2)) * 4u;
            cp16(dst, Asrc + (size_t)gr * 128 + kb + q * 4);
        }
#pragma unroll
        for (int i = 0; i < 4; i++) {           // B: 32x64 fl = 512 f4
            int idx = tid + i * 128;
            int k = idx >> 4, q = idx & 15;
            uint32_t dst = bBase + (uint32_t)(k * 64 + q * 4) * 4u;
            cp16(dst, Wlin + (size_t)(c * 32 + k) * 64 + q * 4);
        }
        asm volatile("cp.async.commit_group;");
    };

    float acc[8][4];
#pragma unroll
    for (int i = 0; i < 8; i++)
#pragma unroll
        for (int j = 0; j < 4; j++) acc[i][j] = 0.f;

    load_chunk(0, 0);

    for (int c = 0; c < 8; c++) {
        int s = c & 1;
        if (c < 7) {
            load_chunk(c + 1, s ^ 1);
            asm volatile("cp.async.wait_group 1;");
        } else {
            asm volatile("cp.async.wait_group 0;");
        }
        __syncthreads();
        const float* Asf = sm + s * GO_STG;
        const float* Bsf = Asf + GO_STG_A;
#pragma unroll 2
        for (int kq = 0; kq < 8; kq++) {
            float4 a4[8];
#pragma unroll
            for (int i = 0; i < 8; i++) {
                int r = ty * 8 + i;
                a4[i] = *(const float4*)(Asf + r * 32 + ((kq ^ (r & 7)) << 2));
            }
#pragma unroll
            for (int kk = 0; kk < 4; kk++) {
                int k = kq * 4 + kk;
                float4 b0 = *(const float4*)(Bsf + k * 64 + 4 * tx);
                float a[8];
#pragma unroll
                for (int i = 0; i < 8; i++)
                    a[i] = (kk == 0) ? a4[i].x : (kk == 1) ? a4[i].y
                         : (kk == 2) ? a4[i].z : a4[i].w;
#pragma unroll
                for (int i = 0; i < 8; i++) {
                    acc[i][0] = fmaf(a[i], b0.x, acc[i][0]);
                    acc[i][1] = fmaf(a[i], b0.y, acc[i][1]);
                    acc[i][2] = fmaf(a[i], b0.z, acc[i][2]);
                    acc[i][3] = fmaf(a[i], b0.w, acc[i][3]);
                }
            }
        }
        __syncthreads();
    }

    float bb[4] = {blin[4 * tx], blin[4 * tx + 1], blin[4 * tx + 2], blin[4 * tx + 3]};
#pragma unroll
    for (int i = 0; i < 8; i++) {
        int r = row0 + ty * 8 + i;
        if (r < M) {
            *(float4*)(out + (size_t)r * 64 + 4 * tx) =
                make_float4(acc[i][0] + bb[0], acc[i][1] + bb[1],
                            acc[i][2] + bb[2], acc[i][3] + bb[3]);
        }
    }
}

// ------------------------- per-edge helpers / agg ---------------------------

__device__ __forceinline__ void agg_step(const float4& u, const float4& b,
                                         const float4& v, float4& s, float4& mx) {
    float m0 = fmaxf(u.x - v.x + b.x, 0.f);
    float m1 = fmaxf(u.y - v.y + b.y, 0.f);
    float m2 = fmaxf(u.z - v.z + b.z, 0.f);
    float m3 = fmaxf(u.w - v.w + b.w, 0.f);
    s.x += m0; s.y += m1; s.z += m2; s.w += m3;
    mx.x = fmaxf(mx.x, m0); mx.y = fmaxf(mx.y, m1);
    mx.z = fmaxf(mx.z, m2); mx.w = fmaxf(mx.w, m3);
}

__global__ __launch_bounds__(256) void agg_kernel(
    const float* __restrict__ U, const float* __restrict__ V,
    const float* __restrict__ bias, int n, int final_mode)
{
    int gw = (blockIdx.x * blockDim.x + threadIdx.x) >> 5;
    int lane = threadIdx.x & 31;
    if (gw >= n) return;
    int start = g_rowptr[gw], end = g_rowptr[gw + 1];
    float4 u = *(const float4*)(U + (size_t)gw * 128 + lane * 4);
    float4 b = *(const float4*)(bias + lane * 4);
    float4 s  = make_float4(0.f, 0.f, 0.f, 0.f);
    float4 mx = make_float4(0.f, 0.f, 0.f, 0.f);
    for (int c = start; c < end; c += 32) {
        int cnt = end - c; if (cnt > 32) cnt = 32;
        int myj = g_sortedJ[c + (lane < cnt ? lane : 0)];
        int t = 0;
        for (; t + 4 <= cnt; t += 4) {
            int j0 = __shfl_sync(0xffffffffu, myj, t);
            int j1 = __shfl_sync(0xffffffffu, myj, t + 1);
            int j2 = __shfl_sync(0xffffffffu, myj, t + 2);
            int j3 = __shfl_sync(0xffffffffu, myj, t + 3);
            float4 v0 = *(const float4*)(V + (size_t)j0 * 128 + lane * 4);
            float4 v1 = *(const float4*)(V + (size_t)j1 * 128 + lane * 4);
            float4 v2 = *(const float4*)(V + (size_t)j2 * 128 + lane * 4);
            float4 v3 = *(const float4*)(V + (size_t)j3 * 128 + lane * 4);
            agg_step(u, b, v0, s, mx);
            agg_step(u, b, v1, s, mx);
            agg_step(u, b, v2, s, mx);
            agg_step(u, b, v3, s, mx);
        }
        for (; t < cnt; t++) {
            int j0 = __shfl_sync(0xffffffffu, myj, t);
            float4 v0 = *(const float4*)(V + (size_t)j0 * 128 + lane * 4);
            agg_step(u, b, v0, s, mx);
        }
    }
    float4 msg = make_float4(s.x * mx.x, s.y * mx.y, s.z * mx.z, s.w * mx.w);
    float* hp = g_hatom + (size_t)gw * 128 + lane * 4;
    float4 h = *(float4*)hp;
    if (!final_mode) {
        h.x *= msg.x; h.y *= msg.y; h.z *= msg.z; h.w *= msg.w;
        *(float4*)hp = h;
    } else {
        float4 o = make_float4(h.x * h.x * msg.x, h.y * h.y * msg.y,
                               h.z * h.z * msg.z, h.w * h.w * msg.w);
        *(float4*)(g_hbondN + (size_t)gw * 128 + lane * 4) = o;
    }
}

__global__ __launch_bounds__(256) void agg0_kernel(
    const float* __restrict__ eattr, const float* __restrict__ Wb,
    const float* __restrict__ bb, int n)
{
    __shared__ float Wbs[16][128];
    for (int i = threadIdx.x; i < 512; i += 256)
        ((float4*)Wbs)[i] = ((const float4*)Wb)[i];
    __syncthreads();
    int gw = (blockIdx.x * blockDim.x + threadIdx.x) >> 5;
    int lane = threadIdx.x & 31;
    if (gw >= n) return;
    int start = g_rowptr[gw], end = g_rowptr[gw + 1];
    float4 b = *(const float4*)(bb + lane * 4);
    float4 s  = make_float4(0.f, 0.f, 0.f, 0.f);
    float4 mx = make_float4(0.f, 0.f, 0.f, 0.f);
    for (int c = start; c < end; c += 32) {
        int cnt = end - c; if (cnt > 32) cnt = 32;
        int myE = g_sortedE[c + (lane < cnt ? lane : 0)];
        for (int t = 0; t < cnt; t++) {
            int eid = __shfl_sync(0xffffffffu, myE, t);
            const float4* ea = (const float4*)(eattr + (size_t)eid * 16);
            float ec[16];
            *(float4*)(&ec[0])  = ea[0];
            *(float4*)(&ec[4])  = ea[1];
            *(float4*)(&ec[8])  = ea[2];
            *(float4*)(&ec[12]) = ea[3];
            float4 m = b;
#pragma unroll
            for (int q = 0; q < 16; q++) {
                float4 w = *(const float4*)(&Wbs[q][lane * 4]);
                m.x = fmaf(ec[q], w.x, m.x);
                m.y = fmaf(ec[q], w.y, m.y);
                m.z = fmaf(ec[q], w.z, m.z);
                m.w = fmaf(ec[q], w.w, m.w);
            }
            m.x = fmaxf(m.x, 0.f); m.y = fmaxf(m.y, 0.f);
            m.z = fmaxf(m.z, 0.f); m.w = fmaxf(m.w, 0.f);
            s.x += m.x; s.y += m.y; s.z += m.z; s.w += m.w;
            mx.x = fmaxf(mx.x, m.x); mx.y = fmaxf(mx.y, m.y);
            mx.z = fmaxf(mx.z, m.z); mx.w = fmaxf(mx.w, m.w);
        }
    }
    float4 xp = *(const float4*)(g_xproj + (size_t)gw * 128 + lane * 4);
    float4 o = make_float4(xp.x * s.x * mx.x, xp.y * s.y * mx.y,
                           xp.z * s.z * mx.z, xp.w * s.w * mx.w);
    *(float4*)(g_hatom + (size_t)gw * 128 + lane * 4) = o;
}

__global__ __launch_bounds__(256) void bond0_kernel(
    const float* __restrict__ eattr, const float* __restrict__ Wb,
    const float* __restrict__ bb, int n)
{
    __shared__ float Wbs[16][128];
    for (int i = threadIdx.x; i < 512; i += 256)
        ((float4*)Wbs)[i] = ((const float4*)Wb)[i];
    __syncthreads();
    int v = (blockIdx.x * blockDim.x + threadIdx.x) >> 5;
    int lane = threadIdx.x & 31;
    if (v >= n) return;
    float4 m = *(const float4*)(bb + lane * 4);
    const float4* ea = (const float4*)(eattr + (size_t)v * 16);
    float ec[16];
    *(float4*)(&ec[0])  = ea[0];
    *(float4*)(&ec[4])  = ea[1];
    *(float4*)(&ec[8])  = ea[2];
    *(float4*)(&ec[12]) = ea[3];
#pragma unroll
    for (int q = 0; q < 16; q++) {
        float4 w = *(const float4*)(&Wbs[q][lane * 4]);
        m.x = fmaf(ec[q], w.x, m.x);
        m.y = fmaf(ec[q], w.y, m.y);
        m.z = fmaf(ec[q], w.z, m.z);
        m.w = fmaf(ec[q], w.w, m.w);
    }
    m.x = fmaxf(m.x, 0.f); m.y = fmaxf(m.y, 0.f);
    m.z = fmaxf(m.z, 0.f); m.w = fmaxf(m.w, 0.f);
    *(float4*)(g_hbondN + (size_t)v * 128 + lane * 4) = m;
}

__global__ __launch_bounds__(256) void bond_update_kernel(
    const float* __restrict__ bias, int n)
{
    int v = (blockIdx.x * blockDim.x + threadIdx.x) >> 5;
    int lane = threadIdx.x & 31;
    if (v >= n) return;
    int i = g_idxI[v], j = g_idxJ[v];
    float4 u  = *(const float4*)(g_U + (size_t)i * 128 + lane * 4);
    float4 vv = *(const float4*)(g_V + (size_t)j * 128 + lane * 4);
    float4 b  = *(const float4*)(bias + lane * 4);
    float4 o = make_float4(fmaxf(u.x - vv.x + b.x, 0.f),
                           fmaxf(u.y - vv.y + b.y, 0.f),
                           fmaxf(u.z - vv.z + b.z, 0.f),
                           fmaxf(u.w - vv.w + b.w, 0.f));
    *(float4*)(g_hbondN + (size_t)v * 128 + lane * 4) = o;
}

// --------------------------------- launch -----------------------------------

extern "C" void kernel_launch(void* const* d_in, const int* in_sizes, int n_in,
                              void* d_out, int out_size) {
    const float* x      = (const float*)d_in[0];
    const int*   eraw   = (const int*)d_in[1];
    const float* eattr  = (const float*)d_in[2];
    const float* W_atom = (const float*)d_in[3];
    const float* b_atom = (const float*)d_in[4];
    const float* W_bond = (const float*)d_in[5];
    const float* b_bond = (const float*)d_in[6];
    const float* W_seq  = (const float*)d_in[7];
    const float* b_seq  = (const float*)d_in[8];
    const float* W_lin  = (const float*)d_in[9];
    const float* b_lin  = (const float*)d_in[10];
    float* out = (float*)d_out;

    int n = in_sizes[0] / 128;   // 30000
    int e = in_sizes[2] / 16;    // 480000
    if (n > NN_MAX) n = NN_MAX;
    if (e > EE_MAX) e = EE_MAX;

    float *p_xproj, *p_hatom, *p_hbondN, *p_U, *p_V;
    cudaGetSymbolAddress((void**)&p_xproj,  g_xproj);
    cudaGetSymbolAddress((void**)&p_hatom,  g_hatom);
    cudaGetSymbolAddress((void**)&p_hbondN, g_hbondN);
    cudaGetSymbolAddress((void**)&p_U,      g_U);
    cudaGetSymbolAddress((void**)&p_V,      g_V);

    static int smem_set = 0;
    if (!smem_set) {
        cudaFuncSetAttribute(gemm64_kernel,
                             cudaFuncAttributeMaxDynamicSharedMemorySize, G64_SMEM);
        cudaFuncSetAttribute(gemm_out_kernel,
                             cudaFuncAttributeMaxDynamicSharedMemorySize, GO_SMEM);
        smem_set = 1;
    }

    int eb  = (e + 255) / 256;
    int nb  = (n + 255) / 256;
    int nwb = (n * 32 + 255) / 256;     // warp-per-node grids
    int g64 = (n + 63) / 64;            // BM=64 GEMM row blocks

    // CSR build + xproj GEMM 4th (ncu capture slot profiles the GEMM)
    init_kernel<<<nb, 256>>>(eraw, e, n);
    convert_hist_kernel<<<eb, 256>>>(eraw, e);
    scan_kernel<<<1, 1024>>>(n);
    // x_proj = relu(x @ W_atom + b_atom)
    gemm64_kernel<<<g64, 256, G64_SMEM>>>(x, x, W_atom, b_atom,
                                          p_xproj, p_xproj, n, g64, 1);
    scatter_kernel<<<eb, 256>>>(e);

    // h_bondN_0 = relu(edge_attr[0:n] @ W_bond + b_bond)
    bond0_kernel<<<nwb, 256>>>(eattr, W_bond, b_bond, n);
    // msg_0 (fused matvec over edges) and h_atom_1 = x_proj * msg_0
    agg0_kernel<<<nwb, 256>>>(eattr, W_bond, b_bond, n);

    for (int l = 0; l < 3; l++) {
        const float* Wl = W_seq + (size_t)l * 128 * 128;
        const float* bl = b_seq + (size_t)l * 128;
        // U = h_atom @ W_l ; V = h_bondN @ W_l  (one dual-source launch)
        gemm64_kernel<<<2 * g64, 256, G64_SMEM>>>(p_hatom, p_hbondN, Wl,
                                                  (const float*)0,
                                                  p_U, p_V, n, g64, 0);
        // h_bondN_{l+1}[v] = relu(U[i_v] - V[j_v] + b_l)  (not needed after l=1)
        if (l < 2) bond_update_kernel<<<nwb, 256>>>(bl, n);
        // msg: l<2 -> h_atom *= msg ; l==2 -> hfin = h_atom^2 * msg (into g_hbondN)
        agg_kernel<<<nwb, 256>>>(p_U, p_V, bl, n, (l == 2) ? 1 : 0);
    }

    // out = [hfin | x_proj] @ W_lin + b_lin
    gemm_out_kernel<<<g64, 128, GO_SMEM>>>(W_lin, b_lin, out, n);
}

// round 13
// speedup vs baseline: 1.0264x; 1.0264x over previous
#include <cuda_runtime.h>
#include <cstdint>

// ---------------------------------------------------------------------------
// CMPNN, restructured:
//   x_proj = relu(x @ W_atom + b)                         [N,128]
//   loop l=0..2:
//     msg[i] = sum_e m_e * max_e m_e ; h_atom *= msg
//     U = h_atom @ W_l ; V = h_bondN @ W_l                [N,128] each
//     h_bondN[v] = relu(U[iI[v]] - V[iJ[v]] + b_l)  (rows < N only)
//   final msg -> hfin = h_atom^2 * msg
//   out = [hfin | x_proj] @ W_lin + b_lin                 [N,64]
// GEMMs: scalar FFMA, BM=64 tiles, 128 threads x (8x8) accumulators,
// cp.async double-buffered chunks + double-buffered (software-pipelined)
// A-fragment LDS.128 loads to hide shared-memory latency.
// h_bond [E,128] is never materialized: m_e = relu(U[i_e]-V[j_e]+b).
// ---------------------------------------------------------------------------

#define NN_MAX 30000
#define EE_MAX 480000

__device__ int g_is64;
__device__ int g_idxI[EE_MAX];
__device__ int g_idxJ[EE_MAX];
__device__ int g_deg[NN_MAX];
__device__ int g_rowptr[NN_MAX + 1];
__device__ int g_cursor[NN_MAX];
__device__ int g_sortedJ[EE_MAX];
__device__ int g_sortedE[EE_MAX];

__device__ __align__(16) float g_xproj[NN_MAX * 128];
__device__ __align__(16) float g_hatom[NN_MAX * 128];
__device__ __align__(16) float g_hbondN[NN_MAX * 128];
__device__ __align__(16) float g_U[NN_MAX * 128];
__device__ __align__(16) float g_V[NN_MAX * 128];

// ------------------------------- index setup -------------------------------

__global__ void init_kernel(const int* __restrict__ raw, int e, int n) {
    if (blockIdx.x == 0) {
        __shared__ int nz;
        if (threadIdx.x == 0) nz = 0;
        __syncthreads();
        int K = e < 2048 ? e : 2048;
        for (int t = threadIdx.x; t < K; t += blockDim.x)
            if (raw[2 * t + 1] != 0) nz = 1;
        __syncthreads();
        if (threadIdx.x == 0) g_is64 = (nz == 0) ? 1 : 0;
    }
    int t = blockIdx.x * blockDim.x + threadIdx.x;
    if (t < n) g_deg[t] = 0;
}

__global__ void convert_hist_kernel(const int* __restrict__ raw, int e) {
    int t = blockIdx.x * blockDim.x + threadIdx.x;
    if (t >= e) return;
    int i, j;
    if (g_is64) { i = raw[2 * t]; j = raw[2 * (e + t)]; }
    else        { i = raw[t];     j = raw[e + t]; }
    g_idxI[t] = i;
    g_idxJ[t] = j;
    atomicAdd(&g_deg[i], 1);
}

// Single-block exclusive scan, thread-coarsened + warp shuffles.
__global__ __launch_bounds__(1024) void scan_kernel(int n) {
    const int ITEMS = 32;                 // 1024*32 = 32768 >= NN_MAX
    __shared__ int wsum[32];
    int t = threadIdx.x;
    int base = t * ITEMS;
    int pre[ITEMS];
    int tot = 0;
#pragma unroll
    for (int i = 0; i < ITEMS; i++) {
        int idx = base + i;
        int d = (idx < n) ? g_deg[idx] : 0;
        pre[i] = tot;
        tot += d;
    }
    int lane = t & 31, wid = t >> 5;
    int incl = tot;
#pragma unroll
    for (int o = 1; o < 32; o <<= 1) {
        int v = __shfl_up_sync(0xffffffffu, incl, o);
        if (lane >= o) incl += v;
    }
    if (lane == 31) wsum[wid] = incl;
    __syncthreads();
    if (wid == 0) {
        int v = wsum[lane];
#pragma unroll
        for (int o = 1; o < 32; o <<= 1) {
            int u = __shfl_up_sync(0xffffffffu, v, o);
            if (lane >= o) v += u;
        }
        wsum[lane] = v;
    }
    __syncthreads();
    int warp_off = (wid > 0) ? wsum[wid - 1] : 0;
    int excl = warp_off + incl - tot;
#pragma unroll
    for (int i = 0; i < ITEMS; i++) {
        int idx = base + i;
        if (idx < n) {
            int p = excl + pre[i];
            g_rowptr[idx] = p;
            g_cursor[idx] = p;
        }
    }
    if (t == 1023) g_rowptr[n] = warp_off + incl;
}

__global__ void scatter_kernel(int e) {
    int t = blockIdx.x * blockDim.x + threadIdx.x;
    if (t >= e) return;
    int i = g_idxI[t];
    int p = atomicAdd(&g_cursor[i], 1);
    g_sortedJ[p] = g_idxJ[t];
    g_sortedE[p] = t;
}

// ------------------------------ 64-row SGEMM --------------------------------
// C[M,128] = act(A[M,128] @ W[128,128] + bias), BM=64 per CTA, 128 threads.
// Dual-source: blocks < nblk use (A1,C1), the rest (A2,C2).
// cp.async 2-stage pipeline over BK=32 chunks. Conflict-free smem:
//   A stage [64][32] row-major, quad q of row r stored at q^(r&7);
//   A fragments double-buffered across k-quads (prefetch kq+1 during kq's
//   128 FFMAs) so the 29-cyc LDS latency is covered inside one warp.
// Thread (tx=tid&15, ty=tid>>4) owns rows ty*8..+7, cols {4tx..+3, 64+4tx..+3}.

#define G64_STG_A (64 * 32)                 // floats
#define G64_STG_B (32 * 128)                // floats
#define G64_STG   (G64_STG_A + G64_STG_B)   // 6144 floats = 24 KB
#define G64_SMEM  (2 * G64_STG * 4)         // 48 KB

__device__ __forceinline__ uint32_t smem_u32(const void* p) {
    uint32_t a;
    asm("{ .reg .u64 t; cvta.to.shared.u64 t, %1; cvt.u32.u64 %0, t; }"
        : "=r"(a) : "l"(p));
    return a;
}
__device__ __forceinline__ void cp16(uint32_t dst, const void* src) {
    asm volatile("cp.async.ca.shared.global [%0], [%1], 16;"
                 :: "r"(dst), "l"(src));
}

__global__ __launch_bounds__(128, 3) void gemm64_kernel(
    const float* __restrict__ A1, const float* __restrict__ A2,
    const float* __restrict__ W, const float* __restrict__ bias,
    float* __restrict__ C1, float* __restrict__ C2,
    int M, int nblk, int act)
{
    extern __shared__ float sm[];
    uint32_t sbase = smem_u32(sm);

    const float* __restrict__ A;
    float* __restrict__ C;
    int bx = blockIdx.x;
    if (bx < nblk) { A = A1; C = C1; } else { A = A2; C = C2; bx -= nblk; }
    int row0 = bx * 64;
    int tid = threadIdx.x;
    int tx = tid & 15, ty = tid >> 4;

    auto load_chunk = [&](int c, int s) {
        uint32_t aBase = sbase + (uint32_t)(s * G64_STG) * 4u;
        uint32_t bBase = aBase + (uint32_t)G64_STG_A * 4u;
#pragma unroll
        for (int i = 0; i < 4; i++) {           // A: 64x32 fl = 512 f4
            int idx = tid + i * 128;
            int r = idx >> 3, q = idx & 7;
            int gr = row0 + r; if (gr > M - 1) gr = M - 1;   // tail rows discarded
            uint32_t dst = aBase + (uint32_t)(r * 32 + ((q ^ (r & 7)) << 2)) * 4u;
            cp16(dst, A + (size_t)gr * 128 + c * 32 + q * 4);
        }
#pragma unroll
        for (int i = 0; i < 8; i++) {           // B: 32x128 fl = 1024 f4
            int idx = tid + i * 128;
            int k = idx >> 5, q = idx & 31;
            uint32_t dst = bBase + (uint32_t)(k * 128 + q * 4) * 4u;
            cp16(dst, W + (size_t)(c * 32 + k) * 128 + q * 4);
        }
        asm volatile("cp.async.commit_group;");
    };

    float acc[8][8];
#pragma unroll
    for (int i = 0; i < 8; i++)
#pragma unroll
        for (int j = 0; j < 8; j++) acc[i][j] = 0.f;

    load_chunk(0, 0);

    for (int c = 0; c < 4; c++) {
        int s = c & 1;
        if (c < 3) {
            load_chunk(c + 1, s ^ 1);
            asm volatile("cp.async.wait_group 1;");
        } else {
            asm volatile("cp.async.wait_group 0;");
        }
        __syncthreads();
        const float* Asf = sm + s * G64_STG;
        const float* Bsf = Asf + G64_STG_A;

        float4 a4[2][8];
        // prologue: fragments for kq=0  (row = ty*8+i -> r&7 == i)
#pragma unroll
        for (int i = 0; i < 8; i++)
            a4[0][i] = *(const float4*)(Asf + (ty * 8 + i) * 32 + ((0 ^ i) << 2));

#pragma unroll 2
        for (int kq = 0; kq < 8; kq++) {        // k-quad: 4 k-steps
            int cur = kq & 1, nxt = cur ^ 1;
            int kqn = (kq < 7) ? kq + 1 : 7;    // clamped prefetch (last is dead)
#pragma unroll
            for (int i = 0; i < 8; i++)
                a4[nxt][i] = *(const float4*)(Asf + (ty * 8 + i) * 32 + ((kqn ^ i) << 2));
#pragma unroll
            for (int kk = 0; kk < 4; kk++) {
                int k = kq * 4 + kk;
                float4 b0 = *(const float4*)(Bsf + k * 128 + 4 * tx);
                float4 b1 = *(const float4*)(Bsf + k * 128 + 64 + 4 * tx);
                float a[8];
#pragma unroll
                for (int i = 0; i < 8; i++)
                    a[i] = (kk == 0) ? a4[cur][i].x : (kk == 1) ? a4[cur][i].y
                         : (kk == 2) ? a4[cur][i].z : a4[cur][i].w;
#pragma unroll
                for (int i = 0; i < 8; i++) {
                    acc[i][0] = fmaf(a[i], b0.x, acc[i][0]);
                    acc[i][1] = fmaf(a[i], b0.y, acc[i][1]);
                    acc[i][2] = fmaf(a[i], b0.z, acc[i][2]);
                    acc[i][3] = fmaf(a[i], b0.w, acc[i][3]);
                    acc[i][4] = fmaf(a[i], b1.x, acc[i][4]);
                    acc[i][5] = fmaf(a[i], b1.y, acc[i][5]);
                    acc[i][6] = fmaf(a[i], b1.z, acc[i][6]);
                    acc[i][7] = fmaf(a[i], b1.w, acc[i][7]);
                }
            }
        }
        __syncthreads();
    }

    float bb[8];
    if (bias) {
#pragma unroll
        for (int j = 0; j < 4; j++) { bb[j] = bias[4 * tx + j]; bb[4 + j] = bias[64 + 4 * tx + j]; }
    } else {
#pragma unroll
        for (int j = 0; j < 8; j++) bb[j] = 0.f;
    }
#pragma unroll
    for (int i = 0; i < 8; i++) {
        int r = row0 + ty * 8 + i;
        if (r < M) {
            float v[8];
#pragma unroll
            for (int j = 0; j < 8; j++) {
                float t = acc[i][j] + bb[j];
                v[j] = act ? fmaxf(t, 0.f) : t;
            }
            float* op = C + (size_t)r * 128;
            *(float4*)(op + 4 * tx)      = make_float4(v[0], v[1], v[2], v[3]);
            *(float4*)(op + 64 + 4 * tx) = make_float4(v[4], v[5], v[6], v[7]);
        }
    }
}

// -------------------------- out GEMM (BM=64, N=64) ---------------------------
// out[N,64] = [hfin | xproj] @ W_lin[256,64] + b_lin. K=256 in 8 chunks;
// chunks 0-3 read g_hbondN (hfin), 4-7 g_xproj. 128 threads, 8x4 acc.

#define GO_STG_A (64 * 32)
#define GO_STG_B (32 * 64)
#define GO_STG   (GO_STG_A + GO_STG_B)      // 4096 floats = 16 KB
#define GO_SMEM  (2 * GO_STG * 4)           // 32 KB

__global__ __launch_bounds__(128) void gemm_out_kernel(
    const float* __restrict__ Wlin, const float* __restrict__ blin,
    float* __restrict__ out, int M)
{
    extern __shared__ float sm[];
    uint32_t sbase = smem_u32(sm);
    int row0 = blockIdx.x * 64;
    int tid = threadIdx.x;
    int tx = tid & 15, ty = tid >> 4;

    auto load_chunk = [&](int c, int s) {
        const float* Asrc = (c < 4) ? g_hbondN : g_xproj;
        int kb = (c & 3) * 32;
        uint32_t aBase = sbase + (uint32_t)(s * GO_STG) * 4u;
        uint32_t bBase = aBase + (uint32_t)GO_STG_A * 4u;
#pragma unroll
        for (int i = 0; i < 4; i++) {           // A: 64x32 fl = 512 f4
            int idx = tid + i * 128;
            int r = idx >> 3, q = idx & 7;
            int gr = row0 + r; if (gr > M - 1) gr = M - 1;
            uint32_t dst = aBase + (uint32_t)(r * 32 + ((q ^ (r & 7)) << 2)) * 4u;
            cp16(dst, Asrc + (size_t)gr * 128 + kb + q * 4);
        }
#pragma unroll
        for (int i = 0; i < 4; i++) {           // B: 32x64 fl = 512 f4
            int idx = tid + i * 128;
            int k = idx >> 4, q = idx & 15;
            uint32_t dst = bBase + (uint32_t)(k * 64 + q * 4) * 4u;
            cp16(dst, Wlin + (size_t)(c * 32 + k) * 64 + q * 4);
        }
        asm volatile("cp.async.commit_group;");
    };

    float acc[8][4];
#pragma unroll
    for (int i = 0; i < 8; i++)
#pragma unroll
        for (int j = 0; j < 4; j++) acc[i][j] = 0.f;

    load_chunk(0, 0);

    for (int c = 0; c < 8; c++) {
        int s = c & 1;
        if (c < 7) {
            load_chunk(c + 1, s ^ 1);
            asm volatile("cp.async.wait_group 1;");
        } else {
            asm volatile("cp.async.wait_group 0;");
        }
        __syncthreads();
        const float* Asf = sm + s * GO_STG;
        const float* Bsf = Asf + GO_STG_A;
#pragma unroll 2
        for (int kq = 0; kq < 8; kq++) {
            float4 a4[8];
#pragma unroll
            for (int i = 0; i < 8; i++) {
                int r = ty * 8 + i;
                a4[i] = *(const float4*)(Asf + r * 32 + ((kq ^ (r & 7)) << 2));
            }
#pragma unroll
            for (int kk = 0; kk < 4; kk++) {
                int k = kq * 4 + kk;
                float4 b0 = *(const float4*)(Bsf + k * 64 + 4 * tx);
                float a[8];
#pragma unroll
                for (int i = 0; i < 8; i++)
                    a[i] = (kk == 0) ? a4[i].x : (kk == 1) ? a4[i].y
                         : (kk == 2) ? a4[i].z : a4[i].w;
#pragma unroll
                for (int i = 0; i < 8; i++) {
                    acc[i][0] = fmaf(a[i], b0.x, acc[i][0]);
                    acc[i][1] = fmaf(a[i], b0.y, acc[i][1]);
                    acc[i][2] = fmaf(a[i], b0.z, acc[i][2]);
                    acc[i][3] = fmaf(a[i], b0.w, acc[i][3]);
                }
            }
        }
        __syncthreads();
    }

    float bb[4] = {blin[4 * tx], blin[4 * tx + 1], blin[4 * tx + 2], blin[4 * tx + 3]};
#pragma unroll
    for (int i = 0; i < 8; i++) {
        int r = row0 + ty * 8 + i;
        if (r < M) {
            *(float4*)(out + (size_t)r * 64 + 4 * tx) =
                make_float4(acc[i][0] + bb[0], acc[i][1] + bb[1],
                            acc[i][2] + bb[2], acc[i][3] + bb[3]);
        }
    }
}

// ------------------------- per-edge helpers / agg ---------------------------

__device__ __forceinline__ void agg_step(const float4& u, const float4& b,
                                         const float4& v, float4& s, float4& mx) {
    float m0 = fmaxf(u.x - v.x + b.x, 0.f);
    float m1 = fmaxf(u.y - v.y + b.y, 0.f);
    float m2 = fmaxf(u.z - v.z + b.z, 0.f);
    float m3 = fmaxf(u.w - v.w + b.w, 0.f);
    s.x += m0; s.y += m1; s.z += m2; s.w += m3;
    mx.x = fmaxf(mx.x, m0); mx.y = fmaxf(mx.y, m1);
    mx.z = fmaxf(mx.z, m2); mx.w = fmaxf(mx.w, m3);
}

__global__ __launch_bounds__(256) void agg_kernel(
    const float* __restrict__ U, const float* __restrict__ V,
    const float* __restrict__ bias, int n, int final_mode)
{
    int gw = (blockIdx.x * blockDim.x + threadIdx.x) >> 5;
    int lane = threadIdx.x & 31;
    if (gw >= n) return;
    int start = g_rowptr[gw], end = g_rowptr[gw + 1];
    float4 u = *(const float4*)(U + (size_t)gw * 128 + lane * 4);
    float4 b = *(const float4*)(bias + lane * 4);
    float4 s  = make_float4(0.f, 0.f, 0.f, 0.f);
    float4 mx = make_float4(0.f, 0.f, 0.f, 0.f);
    for (int c = start; c < end; c += 32) {
        int cnt = end - c; if (cnt > 32) cnt = 32;
        int myj = g_sortedJ[c + (lane < cnt ? lane : 0)];
        int t = 0;
        for (; t + 4 <= cnt; t += 4) {
            int j0 = __shfl_sync(0xffffffffu, myj, t);
            int j1 = __shfl_sync(0xffffffffu, myj, t + 1);
            int j2 = __shfl_sync(0xffffffffu, myj, t + 2);
            int j3 = __shfl_sync(0xffffffffu, myj, t + 3);
            float4 v0 = *(const float4*)(V + (size_t)j0 * 128 + lane * 4);
            float4 v1 = *(const float4*)(V + (size_t)j1 * 128 + lane * 4);
            float4 v2 = *(const float4*)(V + (size_t)j2 * 128 + lane * 4);
            float4 v3 = *(const float4*)(V + (size_t)j3 * 128 + lane * 4);
            agg_step(u, b, v0, s, mx);
            agg_step(u, b, v1, s, mx);
            agg_step(u, b, v2, s, mx);
            agg_step(u, b, v3, s, mx);
        }
        for (; t < cnt; t++) {
            int j0 = __shfl_sync(0xffffffffu, myj, t);
            float4 v0 = *(const float4*)(V + (size_t)j0 * 128 + lane * 4);
            agg_step(u, b, v0, s, mx);
        }
    }
    float4 msg = make_float4(s.x * mx.x, s.y * mx.y, s.z * mx.z, s.w * mx.w);
    float* hp = g_hatom + (size_t)gw * 128 + lane * 4;
    float4 h = *(float4*)hp;
    if (!final_mode) {
        h.x *= msg.x; h.y *= msg.y; h.z *= msg.z; h.w *= msg.w;
        *(float4*)hp = h;
    } else {
        float4 o = make_float4(h.x * h.x * msg.x, h.y * h.y * msg.y,
                               h.z * h.z * msg.z, h.w * h.w * msg.w);
        *(float4*)(g_hbondN + (size_t)gw * 128 + lane * 4) = o;
    }
}

__global__ __launch_bounds__(256) void agg0_kernel(
    const float* __restrict__ eattr, const float* __restrict__ Wb,
    const float* __restrict__ bb, int n)
{
    __shared__ float Wbs[16][128];
    for (int i = threadIdx.x; i < 512; i += 256)
        ((float4*)Wbs)[i] = ((const float4*)Wb)[i];
    __syncthreads();
    int gw = (blockIdx.x * blockDim.x + threadIdx.x) >> 5;
    int lane = threadIdx.x & 31;
    if (gw >= n) return;
    int start = g_rowptr[gw], end = g_rowptr[gw + 1];
    float4 b = *(const float4*)(bb + lane * 4);
    float4 s  = make_float4(0.f, 0.f, 0.f, 0.f);
    float4 mx = make_float4(0.f, 0.f, 0.f, 0.f);
    for (int c = start; c < end; c += 32) {
        int cnt = end - c; if (cnt > 32) cnt = 32;
        int myE = g_sortedE[c + (lane < cnt ? lane : 0)];
        for (int t = 0; t < cnt; t++) {
            int eid = __shfl_sync(0xffffffffu, myE, t);
            const float4* ea = (const float4*)(eattr + (size_t)eid * 16);
            float ec[16];
            *(float4*)(&ec[0])  = ea[0];
            *(float4*)(&ec[4])  = ea[1];
            *(float4*)(&ec[8])  = ea[2];
            *(float4*)(&ec[12]) = ea[3];
            float4 m = b;
#pragma unroll
            for (int q = 0; q < 16; q++) {
                float4 w = *(const float4*)(&Wbs[q][lane * 4]);
                m.x = fmaf(ec[q], w.x, m.x);
                m.y = fmaf(ec[q], w.y, m.y);
                m.z = fmaf(ec[q], w.z, m.z);
                m.w = fmaf(ec[q], w.w, m.w);
            }
            m.x = fmaxf(m.x, 0.f); m.y = fmaxf(m.y, 0.f);
            m.z = fmaxf(m.z, 0.f); m.w = fmaxf(m.w, 0.f);
            s.x += m.x; s.y += m.y; s.z += m.z; s.w += m.w;
            mx.x = fmaxf(mx.x, m.x); mx.y = fmaxf(mx.y, m.y);
            mx.z = fmaxf(mx.z, m.z); mx.w = fmaxf(mx.w, m.w);
        }
    }
    float4 xp = *(const float4*)(g_xproj + (size_t)gw * 128 + lane * 4);
    float4 o = make_float4(xp.x * s.x * mx.x, xp.y * s.y * mx.y,
                           xp.z * s.z * mx.z, xp.w * s.w * mx.w);
    *(float4*)(g_hatom + (size_t)gw * 128 + lane * 4) = o;
}

__global__ __launch_bounds__(256) void bond0_kernel(
    const float* __restrict__ eattr, const float* __restrict__ Wb,
    const float* __restrict__ bb, int n)
{
    __shared__ float Wbs[16][128];
    for (int i = threadIdx.x; i < 512; i += 256)
        ((float4*)Wbs)[i] = ((const float4*)Wb)[i];
    __syncthreads();
    int v = (blockIdx.x * blockDim.x + threadIdx.x) >> 5;
    int lane = threadIdx.x & 31;
    if (v >= n) return;
    float4 m = *(const float4*)(bb + lane * 4);
    const float4* ea = (const float4*)(eattr + (size_t)v * 16);
    float ec[16];
    *(float4*)(&ec[0])  = ea[0];
    *(float4*)(&ec[4])  = ea[1];
    *(float4*)(&ec[8])  = ea[2];
    *(float4*)(&ec[12]) = ea[3];
#pragma unroll
    for (int q = 0; q < 16; q++) {
        float4 w = *(const float4*)(&Wbs[q][lane * 4]);
        m.x = fmaf(ec[q], w.x, m.x);
        m.y = fmaf(ec[q], w.y, m.y);
        m.z = fmaf(ec[q], w.z, m.z);
        m.w = fmaf(ec[q], w.w, m.w);
    }
    m.x = fmaxf(m.x, 0.f); m.y = fmaxf(m.y, 0.f);
    m.z = fmaxf(m.z, 0.f); m.w = fmaxf(m.w, 0.f);
    *(float4*)(g_hbondN + (size_t)v * 128 + lane * 4) = m;
}

__global__ __launch_bounds__(256) void bond_update_kernel(
    const float* __restrict__ bias, int n)
{
    int v = (blockIdx.x * blockDim.x + threadIdx.x) >> 5;
    int lane = threadIdx.x & 31;
    if (v >= n) return;
    int i = g_idxI[v], j = g_idxJ[v];
    float4 u  = *(const float4*)(g_U + (size_t)i * 128 + lane * 4);
    float4 vv = *(const float4*)(g_V + (size_t)j * 128 + lane * 4);
    float4 b  = *(const float4*)(bias + lane * 4);
    float4 o = make_float4(fmaxf(u.x - vv.x + b.x, 0.f),
                           fmaxf(u.y - vv.y + b.y, 0.f),
                           fmaxf(u.z - vv.z + b.z, 0.f),
                           fmaxf(u.w - vv.w + b.w, 0.f));
    *(float4*)(g_hbondN + (size_t)v * 128 + lane * 4) = o;
}

// --------------------------------- launch -----------------------------------

extern "C" void kernel_launch(void* const* d_in, const int* in_sizes, int n_in,
                              void* d_out, int out_size) {
    const float* x      = (const float*)d_in[0];
    const int*   eraw   = (const int*)d_in[1];
    const float* eattr  = (const float*)d_in[2];
    const float* W_atom = (const float*)d_in[3];
    const float* b_atom = (const float*)d_in[4];
    const float* W_bond = (const float*)d_in[5];
    const float* b_bond = (const float*)d_in[6];
    const float* W_seq  = (const float*)d_in[7];
    const float* b_seq  = (const float*)d_in[8];
    const float* W_lin  = (const float*)d_in[9];
    const float* b_lin  = (const float*)d_in[10];
    float* out = (float*)d_out;

    int n = in_sizes[0] / 128;   // 30000
    int e = in_sizes[2] / 16;    // 480000
    if (n > NN_MAX) n = NN_MAX;
    if (e > EE_MAX) e = EE_MAX;

    float *p_xproj, *p_hatom, *p_hbondN, *p_U, *p_V;
    cudaGetSymbolAddress((void**)&p_xproj,  g_xproj);
    cudaGetSymbolAddress((void**)&p_hatom,  g_hatom);
    cudaGetSymbolAddress((void**)&p_hbondN, g_hbondN);
    cudaGetSymbolAddress((void**)&p_U,      g_U);
    cudaGetSymbolAddress((void**)&p_V,      g_V);

    static int smem_set = 0;
    if (!smem_set) {
        cudaFuncSetAttribute(gemm64_kernel,
                             cudaFuncAttributeMaxDynamicSharedMemorySize, G64_SMEM);
        cudaFuncSetAttribute(gemm_out_kernel,
                             cudaFuncAttributeMaxDynamicSharedMemorySize, GO_SMEM);
        smem_set = 1;
    }

    int eb  = (e + 255) / 256;
    int nb  = (n + 255) / 256;
    int nwb = (n * 32 + 255) / 256;     // warp-per-node grids
    int g64 = (n + 63) / 64;            // BM=64 GEMM row blocks

    // CSR build + xproj GEMM 4th (ncu capture slot profiles the GEMM)
    init_kernel<<<nb, 256>>>(eraw, e, n);
    convert_hist_kernel<<<eb, 256>>>(eraw, e);
    scan_kernel<<<1, 1024>>>(n);
    // x_proj = relu(x @ W_atom + b_atom)
    gemm64_kernel<<<g64, 128, G64_SMEM>>>(x, x, W_atom, b_atom,
                                          p_xproj, p_xproj, n, g64, 1);
    scatter_kernel<<<eb, 256>>>(e);

    // h_bondN_0 = relu(edge_attr[0:n] @ W_bond + b_bond)
    bond0_kernel<<<nwb, 256>>>(eattr, W_bond, b_bond, n);
    // msg_0 (fused matvec over edges) and h_atom_1 = x_proj * msg_0
    agg0_kernel<<<nwb, 256>>>(eattr, W_bond, b_bond, n);

    for (int l = 0; l < 3; l++) {
        const float* Wl = W_seq + (size_t)l * 128 * 128;
        const float* bl = b_seq + (size_t)l * 128;
        // U = h_atom @ W_l ; V = h_bondN @ W_l  (one dual-source launch)
        gemm64_kernel<<<2 * g64, 128, G64_SMEM>>>(p_hatom, p_hbondN, Wl,
                                                  (const float*)0,
                                                  p_U, p_V, n, g64, 0);
        // h_bondN_{l+1}[v] = relu(U[i_v] - V[j_v] + b_l)  (not needed after l=1)
        if (l < 2) bond_update_kernel<<<nwb, 256>>>(bl, n);
        // msg: l<2 -> h_atom *= msg ; l==2 -> hfin = h_atom^2 * msg (into g_hbondN)
        agg_kernel<<<nwb, 256>>>(p_U, p_V, bl, n, (l == 2) ? 1 : 0);
    }

    // out = [hfin | x_proj] @ W_lin + b_lin
    gemm_out_kernel<<<g64, 128, GO_SMEM>>>(W_lin, b_lin, out, n);
}

// round 14
// speedup vs baseline: 1.0900x; 1.0620x over previous
#include <cuda_runtime.h>
#include <cstdint>

// ---------------------------------------------------------------------------
// CMPNN, restructured:
//   x_proj = relu(x @ W_atom + b)                         [N,128]
//   loop l=0..2:
//     msg[i] = sum_e m_e * max_e m_e ; h_atom *= msg
//     U = h_atom @ W_l ; V = h_bondN @ W_l                [N,128] each
//     h_bondN[v] = relu(U[iI[v]] - V[iJ[v]] + b_l)  (rows < N only)
//   final msg -> hfin = h_atom^2 * msg
//   out = [hfin | x_proj] @ W_lin + b_lin                 [N,64]
// GEMMs: scalar FFMA (R11 shape: 128 thr x 8x8, quad-amortized LDS.128,
// cp.async double-buffered). Dual-stream overlap: xproj+bond0 run
// concurrently with the CSR build; bond_update overlaps agg per layer.
// h_bond [E,128] is never materialized: m_e = relu(U[i_e]-V[j_e]+b).
// ---------------------------------------------------------------------------

#define NN_MAX 30000
#define EE_MAX 480000

__device__ int g_is64;
__device__ int g_idxI[EE_MAX];
__device__ int g_idxJ[EE_MAX];
__device__ int g_deg[NN_MAX];
__device__ int g_rowptr[NN_MAX + 1];
__device__ int g_cursor[NN_MAX];
__device__ int g_sortedJ[EE_MAX];
__device__ int g_sortedE[EE_MAX];

__device__ __align__(16) float g_xproj[NN_MAX * 128];
__device__ __align__(16) float g_hatom[NN_MAX * 128];
__device__ __align__(16) float g_hbondN[NN_MAX * 128];
__device__ __align__(16) float g_U[NN_MAX * 128];
__device__ __align__(16) float g_V[NN_MAX * 128];

// ------------------------------- index setup -------------------------------

__global__ void init_kernel(const int* __restrict__ raw, int e, int n) {
    if (blockIdx.x == 0) {
        __shared__ int nz;
        if (threadIdx.x == 0) nz = 0;
        __syncthreads();
        int K = e < 2048 ? e : 2048;
        for (int t = threadIdx.x; t < K; t += blockDim.x)
            if (raw[2 * t + 1] != 0) nz = 1;
        __syncthreads();
        if (threadIdx.x == 0) g_is64 = (nz == 0) ? 1 : 0;
    }
    int t = blockIdx.x * blockDim.x + threadIdx.x;
    if (t < n) g_deg[t] = 0;
}

__global__ void convert_hist_kernel(const int* __restrict__ raw, int e) {
    int t = blockIdx.x * blockDim.x + threadIdx.x;
    if (t >= e) return;
    int i, j;
    if (g_is64) { i = raw[2 * t]; j = raw[2 * (e + t)]; }
    else        { i = raw[t];     j = raw[e + t]; }
    g_idxI[t] = i;
    g_idxJ[t] = j;
    atomicAdd(&g_deg[i], 1);
}

// Single-block exclusive scan, thread-coarsened + warp shuffles.
__global__ __launch_bounds__(1024) void scan_kernel(int n) {
    const int ITEMS = 32;                 // 1024*32 = 32768 >= NN_MAX
    __shared__ int wsum[32];
    int t = threadIdx.x;
    int base = t * ITEMS;
    int pre[ITEMS];
    int tot = 0;
#pragma unroll
    for (int i = 0; i < ITEMS; i++) {
        int idx = base + i;
        int d = (idx < n) ? g_deg[idx] : 0;
        pre[i] = tot;
        tot += d;
    }
    int lane = t & 31, wid = t >> 5;
    int incl = tot;
#pragma unroll
    for (int o = 1; o < 32; o <<= 1) {
        int v = __shfl_up_sync(0xffffffffu, incl, o);
        if (lane >= o) incl += v;
    }
    if (lane == 31) wsum[wid] = incl;
    __syncthreads();
    if (wid == 0) {
        int v = wsum[lane];
#pragma unroll
        for (int o = 1; o < 32; o <<= 1) {
            int u = __shfl_up_sync(0xffffffffu, v, o);
            if (lane >= o) v += u;
        }
        wsum[lane] = v;
    }
    __syncthreads();
    int warp_off = (wid > 0) ? wsum[wid - 1] : 0;
    int excl = warp_off + incl - tot;
#pragma unroll
    for (int i = 0; i < ITEMS; i++) {
        int idx = base + i;
        if (idx < n) {
            int p = excl + pre[i];
            g_rowptr[idx] = p;
            g_cursor[idx] = p;
        }
    }
    if (t == 1023) g_rowptr[n] = warp_off + incl;
}

__global__ void scatter_kernel(int e) {
    int t = blockIdx.x * blockDim.x + threadIdx.x;
    if (t >= e) return;
    int i = g_idxI[t];
    int p = atomicAdd(&g_cursor[i], 1);
    g_sortedJ[p] = g_idxJ[t];
    g_sortedE[p] = t;
}

// ------------------------------ 64-row SGEMM --------------------------------
// C[M,128] = act(A[M,128] @ W[128,128] + bias), BM=64 per CTA, 128 threads.
// Dual-source: blocks < nblk use (A1,C1), the rest (A2,C2).
// cp.async 2-stage pipeline over BK=32 chunks. Conflict-free smem:
//   A stage [64][32] row-major, quad q of row r stored at q^(r&7);
//   per k-QUAD one LDS.128 per row (broadcast across the 16 lanes sharing ty).
// Thread (tx=tid&15, ty=tid>>4) owns rows ty*8..+7, cols {4tx..+3, 64+4tx..+3}.

#define G64_STG_A (64 * 32)                 // floats
#define G64_STG_B (32 * 128)                // floats
#define G64_STG   (G64_STG_A + G64_STG_B)   // 6144 floats = 24 KB
#define G64_SMEM  (2 * G64_STG * 4)         // 48 KB

__device__ __forceinline__ uint32_t smem_u32(const void* p) {
    uint32_t a;
    asm("{ .reg .u64 t; cvta.to.shared.u64 t, %1; cvt.u32.u64 %0, t; }"
        : "=r"(a) : "l"(p));
    return a;
}
__device__ __forceinline__ void cp16(uint32_t dst, const void* src) {
    asm volatile("cp.async.ca.shared.global [%0], [%1], 16;"
                 :: "r"(dst), "l"(src));
}

__global__ __launch_bounds__(128) void gemm64_kernel(
    const float* __restrict__ A1, const float* __restrict__ A2,
    const float* __restrict__ W, const float* __restrict__ bias,
    float* __restrict__ C1, float* __restrict__ C2,
    int M, int nblk, int act)
{
    extern __shared__ float sm[];
    uint32_t sbase = smem_u32(sm);

    const float* __restrict__ A;
    float* __restrict__ C;
    int bx = blockIdx.x;
    if (bx < nblk) { A = A1; C = C1; } else { A = A2; C = C2; bx -= nblk; }
    int row0 = bx * 64;
    int tid = threadIdx.x;
    int tx = tid & 15, ty = tid >> 4;

    auto load_chunk = [&](int c, int s) {
        uint32_t aBase = sbase + (uint32_t)(s * G64_STG) * 4u;
        uint32_t bBase = aBase + (uint32_t)G64_STG_A * 4u;
#pragma unroll
        for (int i = 0; i < 4; i++) {           // A: 64x32 fl = 512 f4
            int idx = tid + i * 128;
            int r = idx >> 3, q = idx & 7;
            int gr = row0 + r; if (gr > M - 1) gr = M - 1;   // tail rows discarded
            uint32_t dst = aBase + (uint32_t)(r * 32 + ((q ^ (r & 7)) << 2)) * 4u;
            cp16(dst, A + (size_t)gr * 128 + c * 32 + q * 4);
        }
#pragma unroll
        for (int i = 0; i < 8; i++) {           // B: 32x128 fl = 1024 f4
            int idx = tid + i * 128;
            int k = idx >> 5, q = idx & 31;
            uint32_t dst = bBase + (uint32_t)(k * 128 + q * 4) * 4u;
            cp16(dst, W + (size_t)(c * 32 + k) * 128 + q * 4);
        }
        asm volatile("cp.async.commit_group;");
    };

    float acc[8][8];
#pragma unroll
    for (int i = 0; i < 8; i++)
#pragma unroll
        for (int j = 0; j < 8; j++) acc[i][j] = 0.f;

    load_chunk(0, 0);

    for (int c = 0; c < 4; c++) {
        int s = c & 1;
        if (c < 3) {
            load_chunk(c + 1, s ^ 1);
            asm volatile("cp.async.wait_group 1;");
        } else {
            asm volatile("cp.async.wait_group 0;");
        }
        __syncthreads();
        const float* Asf = sm + s * G64_STG;
        const float* Bsf = Asf + G64_STG_A;
#pragma unroll 2
        for (int kq = 0; kq < 8; kq++) {        // k-quad: 4 k-steps
            float4 a4[8];
#pragma unroll
            for (int i = 0; i < 8; i++)
                a4[i] = *(const float4*)(Asf + (ty * 8 + i) * 32 + ((kq ^ i) << 2));
#pragma unroll
            for (int kk = 0; kk < 4; kk++) {
                int k = kq * 4 + kk;
                float4 b0 = *(const float4*)(Bsf + k * 128 + 4 * tx);
                float4 b1 = *(const float4*)(Bsf + k * 128 + 64 + 4 * tx);
                float a[8];
#pragma unroll
                for (int i = 0; i < 8; i++)
                    a[i] = (kk == 0) ? a4[i].x : (kk == 1) ? a4[i].y
                         : (kk == 2) ? a4[i].z : a4[i].w;
#pragma unroll
                for (int i = 0; i < 8; i++) {
                    acc[i][0] = fmaf(a[i], b0.x, acc[i][0]);
                    acc[i][1] = fmaf(a[i], b0.y, acc[i][1]);
                    acc[i][2] = fmaf(a[i], b0.z, acc[i][2]);
                    acc[i][3] = fmaf(a[i], b0.w, acc[i][3]);
                    acc[i][4] = fmaf(a[i], b1.x, acc[i][4]);
                    acc[i][5] = fmaf(a[i], b1.y, acc[i][5]);
                    acc[i][6] = fmaf(a[i], b1.z, acc[i][6]);
                    acc[i][7] = fmaf(a[i], b1.w, acc[i][7]);
                }
            }
        }
        __syncthreads();
    }

    float bb[8];
    if (bias) {
#pragma unroll
        for (int j = 0; j < 4; j++) { bb[j] = bias[4 * tx + j]; bb[4 + j] = bias[64 + 4 * tx + j]; }
    } else {
#pragma unroll
        for (int j = 0; j < 8; j++) bb[j] = 0.f;
    }
#pragma unroll
    for (int i = 0; i < 8; i++) {
        int r = row0 + ty * 8 + i;
        if (r < M) {
            float v[8];
#pragma unroll
            for (int j = 0; j < 8; j++) {
                float t = acc[i][j] + bb[j];
                v[j] = act ? fmaxf(t, 0.f) : t;
            }
            float* op = C + (size_t)r * 128;
            *(float4*)(op + 4 * tx)      = make_float4(v[0], v[1], v[2], v[3]);
            *(float4*)(op + 64 + 4 * tx) = make_float4(v[4], v[5], v[6], v[7]);
        }
    }
}

// -------------------------- out GEMM (BM=64, N=64) ---------------------------
// out[N,64] = [hfin | xproj] @ W_lin[256,64] + b_lin. K=256 in 8 chunks;
// chunks 0-3 read g_hbondN (hfin), 4-7 g_xproj. 128 threads, 8x4 acc.

#define GO_STG_A (64 * 32)
#define GO_STG_B (32 * 64)
#define GO_STG   (GO_STG_A + GO_STG_B)      // 4096 floats = 16 KB
#define GO_SMEM  (2 * GO_STG * 4)           // 32 KB

__global__ __launch_bounds__(128) void gemm_out_kernel(
    const float* __restrict__ Wlin, const float* __restrict__ blin,
    float* __restrict__ out, int M)
{
    extern __shared__ float sm[];
    uint32_t sbase = smem_u32(sm);
    int row0 = blockIdx.x * 64;
    int tid = threadIdx.x;
    int tx = tid & 15, ty = tid >> 4;

    auto load_chunk = [&](int c, int s) {
        const float* Asrc = (c < 4) ? g_hbondN : g_xproj;
        int kb = (c & 3) * 32;
        uint32_t aBase = sbase + (uint32_t)(s * GO_STG) * 4u;
        uint32_t bBase = aBase + (uint32_t)GO_STG_A * 4u;
#pragma unroll
        for (int i = 0; i < 4; i++) {           // A: 64x32 fl = 512 f4
            int idx = tid + i * 128;
            int r = idx >> 3, q = idx & 7;
            int gr = row0 + r; if (gr > M - 1) gr = M - 1;
            uint32_t dst = aBase + (uint32_t)(r * 32 + ((q ^ (r & 7)) << 2)) * 4u;
            cp16(dst, Asrc + (size_t)gr * 128 + kb + q * 4);
        }
#pragma unroll
        for (int i = 0; i < 4; i++) {           // B: 32x64 fl = 512 f4
            int idx = tid + i * 128;
            int k = idx >> 4, q = idx & 15;
            uint32_t dst = bBase + (uint32_t)(k * 64 + q * 4) * 4u;
            cp16(dst, Wlin + (size_t)(c * 32 + k) * 64 + q * 4);
        }
        asm volatile("cp.async.commit_group;");
    };

    float acc[8][4];
#pragma unroll
    for (int i = 0; i < 8; i++)
#pragma unroll
        for (int j = 0; j < 4; j++) acc[i][j] = 0.f;

    load_chunk(0, 0);

    for (int c = 0; c < 8; c++) {
        int s = c & 1;
        if (c < 7) {
            load_chunk(c + 1, s ^ 1);
            asm volatile("cp.async.wait_group 1;");
        } else {
            asm volatile("cp.async.wait_group 0;");
        }
        __syncthreads();
        const float* Asf = sm + s * GO_STG;
        const float* Bsf = Asf + GO_STG_A;
#pragma unroll 2
        for (int kq = 0; kq < 8; kq++) {
            float4 a4[8];
#pragma unroll
            for (int i = 0; i < 8; i++) {
                int r = ty * 8 + i;
                a4[i] = *(const float4*)(Asf + r * 32 + ((kq ^ (r & 7)) << 2));
            }
#pragma unroll
            for (int kk = 0; kk < 4; kk++) {
                int k = kq * 4 + kk;
                float4 b0 = *(const float4*)(Bsf + k * 64 + 4 * tx);
                float a[8];
#pragma unroll
                for (int i = 0; i < 8; i++)
                    a[i] = (kk == 0) ? a4[i].x : (kk == 1) ? a4[i].y
                         : (kk == 2) ? a4[i].z : a4[i].w;
#pragma unroll
                for (int i = 0; i < 8; i++) {
                    acc[i][0] = fmaf(a[i], b0.x, acc[i][0]);
                    acc[i][1] = fmaf(a[i], b0.y, acc[i][1]);
                    acc[i][2] = fmaf(a[i], b0.z, acc[i][2]);
                    acc[i][3] = fmaf(a[i], b0.w, acc[i][3]);
                }
            }
        }
        __syncthreads();
    }

    float bb[4] = {blin[4 * tx], blin[4 * tx + 1], blin[4 * tx + 2], blin[4 * tx + 3]};
#pragma unroll
    for (int i = 0; i < 8; i++) {
        int r = row0 + ty * 8 + i;
        if (r < M) {
            *(float4*)(out + (size_t)r * 64 + 4 * tx) =
                make_float4(acc[i][0] + bb[0], acc[i][1] + bb[1],
                            acc[i][2] + bb[2], acc[i][3] + bb[3]);
        }
    }
}

// ------------------------- per-edge helpers / agg ---------------------------

__device__ __forceinline__ void agg_step(const float4& u, const float4& b,
                                         const float4& v, float4& s, float4& mx) {
    float m0 = fmaxf(u.x - v.x + b.x, 0.f);
    float m1 = fmaxf(u.y - v.y + b.y, 0.f);
    float m2 = fmaxf(u.z - v.z + b.z, 0.f);
    float m3 = fmaxf(u.w - v.w + b.w, 0.f);
    s.x += m0; s.y += m1; s.z += m2; s.w += m3;
    mx.x = fmaxf(mx.x, m0); mx.y = fmaxf(mx.y, m1);
    mx.z = fmaxf(mx.z, m2); mx.w = fmaxf(mx.w, m3);
}

__global__ __launch_bounds__(256) void agg_kernel(
    const float* __restrict__ U, const float* __restrict__ V,
    const float* __restrict__ bias, int n, int final_mode)
{
    int gw = (blockIdx.x * blockDim.x + threadIdx.x) >> 5;
    int lane = threadIdx.x & 31;
    if (gw >= n) return;
    int start = g_rowptr[gw], end = g_rowptr[gw + 1];
    float4 u = *(const float4*)(U + (size_t)gw * 128 + lane * 4);
    float4 b = *(const float4*)(bias + lane * 4);
    float4 s  = make_float4(0.f, 0.f, 0.f, 0.f);
    float4 mx = make_float4(0.f, 0.f, 0.f, 0.f);
    for (int c = start; c < end; c += 32) {
        int cnt = end - c; if (cnt > 32) cnt = 32;
        int myj = g_sortedJ[c + (lane < cnt ? lane : 0)];
        int t = 0;
        for (; t + 4 <= cnt; t += 4) {
            int j0 = __shfl_sync(0xffffffffu, myj, t);
            int j1 = __shfl_sync(0xffffffffu, myj, t + 1);
            int j2 = __shfl_sync(0xffffffffu, myj, t + 2);
            int j3 = __shfl_sync(0xffffffffu, myj, t + 3);
            float4 v0 = *(const float4*)(V + (size_t)j0 * 128 + lane * 4);
            float4 v1 = *(const float4*)(V + (size_t)j1 * 128 + lane * 4);
            float4 v2 = *(const float4*)(V + (size_t)j2 * 128 + lane * 4);
            float4 v3 = *(const float4*)(V + (size_t)j3 * 128 + lane * 4);
            agg_step(u, b, v0, s, mx);
            agg_step(u, b, v1, s, mx);
            agg_step(u, b, v2, s, mx);
            agg_step(u, b, v3, s, mx);
        }
        for (; t < cnt; t++) {
            int j0 = __shfl_sync(0xffffffffu, myj, t);
            float4 v0 = *(const float4*)(V + (size_t)j0 * 128 + lane * 4);
            agg_step(u, b, v0, s, mx);
        }
    }
    float4 msg = make_float4(s.x * mx.x, s.y * mx.y, s.z * mx.z, s.w * mx.w);
    float* hp = g_hatom + (size_t)gw * 128 + lane * 4;
    float4 h = *(float4*)hp;
    if (!final_mode) {
        h.x *= msg.x; h.y *= msg.y; h.z *= msg.z; h.w *= msg.w;
        *(float4*)hp = h;
    } else {
        float4 o = make_float4(h.x * h.x * msg.x, h.y * h.y * msg.y,
                               h.z * h.z * msg.z, h.w * h.w * msg.w);
        *(float4*)(g_hbondN + (size_t)gw * 128 + lane * 4) = o;
    }
}

__global__ __launch_bounds__(256) void agg0_kernel(
    const float* __restrict__ eattr, const float* __restrict__ Wb,
    const float* __restrict__ bb, int n)
{
    __shared__ float Wbs[16][128];
    for (int i = threadIdx.x; i < 512; i += 256)
        ((float4*)Wbs)[i] = ((const float4*)Wb)[i];
    __syncthreads();
    int gw = (blockIdx.x * blockDim.x + threadIdx.x) >> 5;
    int lane = threadIdx.x & 31;
    if (gw >= n) return;
    int start = g_rowptr[gw], end = g_rowptr[gw + 1];
    float4 b = *(const float4*)(bb + lane * 4);
    float4 s  = make_float4(0.f, 0.f, 0.f, 0.f);
    float4 mx = make_float4(0.f, 0.f, 0.f, 0.f);
    for (int c = start; c < end; c += 32) {
        int cnt = end - c; if (cnt > 32) cnt = 32;
        int myE = g_sortedE[c + (lane < cnt ? lane : 0)];
        for (int t = 0; t < cnt; t++) {
            int eid = __shfl_sync(0xffffffffu, myE, t);
            const float4* ea = (const float4*)(eattr + (size_t)eid * 16);
            float ec[16];
            *(float4*)(&ec[0])  = ea[0];
            *(float4*)(&ec[4])  = ea[1];
            *(float4*)(&ec[8])  = ea[2];
            *(float4*)(&ec[12]) = ea[3];
            float4 m = b;
#pragma unroll
            for (int q = 0; q < 16; q++) {
                float4 w = *(const float4*)(&Wbs[q][lane * 4]);
                m.x = fmaf(ec[q], w.x, m.x);
                m.y = fmaf(ec[q], w.y, m.y);
                m.z = fmaf(ec[q], w.z, m.z);
                m.w = fmaf(ec[q], w.w, m.w);
            }
            m.x = fmaxf(m.x, 0.f); m.y = fmaxf(m.y, 0.f);
            m.z = fmaxf(m.z, 0.f); m.w = fmaxf(m.w, 0.f);
            s.x += m.x; s.y += m.y; s.z += m.z; s.w += m.w;
            mx.x = fmaxf(mx.x, m.x); mx.y = fmaxf(mx.y, m.y);
            mx.z = fmaxf(mx.z, m.z); mx.w = fmaxf(mx.w, m.w);
        }
    }
    float4 xp = *(const float4*)(g_xproj + (size_t)gw * 128 + lane * 4);
    float4 o = make_float4(xp.x * s.x * mx.x, xp.y * s.y * mx.y,
                           xp.z * s.z * mx.z, xp.w * s.w * mx.w);
    *(float4*)(g_hatom + (size_t)gw * 128 + lane * 4) = o;
}

__global__ __launch_bounds__(256) void bond0_kernel(
    const float* __restrict__ eattr, const float* __restrict__ Wb,
    const float* __restrict__ bb, int n)
{
    __shared__ float Wbs[16][128];
    for (int i = threadIdx.x; i < 512; i += 256)
        ((float4*)Wbs)[i] = ((const float4*)Wb)[i];
    __syncthreads();
    int v = (blockIdx.x * blockDim.x + threadIdx.x) >> 5;
    int lane = threadIdx.x & 31;
    if (v >= n) return;
    float4 m = *(const float4*)(bb + lane * 4);
    const float4* ea = (const float4*)(eattr + (size_t)v * 16);
    float ec[16];
    *(float4*)(&ec[0])  = ea[0];
    *(float4*)(&ec[4])  = ea[1];
    *(float4*)(&ec[8])  = ea[2];
    *(float4*)(&ec[12]) = ea[3];
#pragma unroll
    for (int q = 0; q < 16; q++) {
        float4 w = *(const float4*)(&Wbs[q][lane * 4]);
        m.x = fmaf(ec[q], w.x, m.x);
        m.y = fmaf(ec[q], w.y, m.y);
        m.z = fmaf(ec[q], w.z, m.z);
        m.w = fmaf(ec[q], w.w, m.w);
    }
    m.x = fmaxf(m.x, 0.f); m.y = fmaxf(m.y, 0.f);
    m.z = fmaxf(m.z, 0.f); m.w = fmaxf(m.w, 0.f);
    *(float4*)(g_hbondN + (size_t)v * 128 + lane * 4) = m;
}

__global__ __launch_bounds__(256) void bond_update_kernel(
    const float* __restrict__ bias, int n)
{
    int v = (blockIdx.x * blockDim.x + threadIdx.x) >> 5;
    int lane = threadIdx.x & 31;
    if (v >= n) return;
    int i = g_idxI[v], j = g_idxJ[v];
    float4 u  = *(const float4*)(g_U + (size_t)i * 128 + lane * 4);
    float4 vv = *(const float4*)(g_V + (size_t)j * 128 + lane * 4);
    float4 b  = *(const float4*)(bias + lane * 4);
    float4 o = make_float4(fmaxf(u.x - vv.x + b.x, 0.f),
                           fmaxf(u.y - vv.y + b.y, 0.f),
                           fmaxf(u.z - vv.z + b.z, 0.f),
                           fmaxf(u.w - vv.w + b.w, 0.f));
    *(float4*)(g_hbondN + (size_t)v * 128 + lane * 4) = o;
}

// --------------------------------- launch -----------------------------------

extern "C" void kernel_launch(void* const* d_in, const int* in_sizes, int n_in,
                              void* d_out, int out_size) {
    const float* x      = (const float*)d_in[0];
    const int*   eraw   = (const int*)d_in[1];
    const float* eattr  = (const float*)d_in[2];
    const float* W_atom = (const float*)d_in[3];
    const float* b_atom = (const float*)d_in[4];
    const float* W_bond = (const float*)d_in[5];
    const float* b_bond = (const float*)d_in[6];
    const float* W_seq  = (const float*)d_in[7];
    const float* b_seq  = (const float*)d_in[8];
    const float* W_lin  = (const float*)d_in[9];
    const float* b_lin  = (const float*)d_in[10];
    float* out = (float*)d_out;

    int n = in_sizes[0] / 128;   // 30000
    int e = in_sizes[2] / 16;    // 480000
    if (n > NN_MAX) n = NN_MAX;
    if (e > EE_MAX) e = EE_MAX;

    float *p_xproj, *p_hatom, *p_hbondN, *p_U, *p_V;
    cudaGetSymbolAddress((void**)&p_xproj,  g_xproj);
    cudaGetSymbolAddress((void**)&p_hatom,  g_hatom);
    cudaGetSymbolAddress((void**)&p_hbondN, g_hbondN);
    cudaGetSymbolAddress((void**)&p_U,      g_U);
    cudaGetSymbolAddress((void**)&p_V,      g_V);

    static cudaStream_t s1 = 0;
    static cudaEvent_t evFork, evSide, evG0, evG1, evBU0, evBU1;
    static int inited = 0;
    if (!inited) {
        cudaFuncSetAttribute(gemm64_kernel,
                             cudaFuncAttributeMaxDynamicSharedMemorySize, G64_SMEM);
        cudaFuncSetAttribute(gemm_out_kernel,
                             cudaFuncAttributeMaxDynamicSharedMemorySize, GO_SMEM);
        cudaStreamCreateWithFlags(&s1, cudaStreamNonBlocking);
        cudaEventCreateWithFlags(&evFork, cudaEventDisableTiming);
        cudaEventCreateWithFlags(&evSide, cudaEventDisableTiming);
        cudaEventCreateWithFlags(&evG0,   cudaEventDisableTiming);
        cudaEventCreateWithFlags(&evG1,   cudaEventDisableTiming);
        cudaEventCreateWithFlags(&evBU0,  cudaEventDisableTiming);
        cudaEventCreateWithFlags(&evBU1,  cudaEventDisableTiming);
        inited = 1;
    }
    cudaEvent_t evG[2]  = {evG0, evG1};
    cudaEvent_t evBU[2] = {evBU0, evBU1};

    int eb  = (e + 255) / 256;
    int nb  = (n + 255) / 256;
    int nwb = (n * 32 + 255) / 256;     // warp-per-node grids
    int g64 = (n + 63) / 64;            // BM=64 GEMM row blocks

    // Fork: side stream runs xproj GEMM + bond0 (independent of the CSR build).
    cudaEventRecord(evFork, 0);
    cudaStreamWaitEvent(s1, evFork, 0);

    // main stream: CSR build
    init_kernel<<<nb, 256>>>(eraw, e, n);
    convert_hist_kernel<<<eb, 256>>>(eraw, e);
    scan_kernel<<<1, 1024>>>(n);
    // side stream: x_proj = relu(x @ W_atom + b_atom)  (4th launch = ncu slot)
    gemm64_kernel<<<g64, 128, G64_SMEM, s1>>>(x, x, W_atom, b_atom,
                                              p_xproj, p_xproj, n, g64, 1);
    scatter_kernel<<<eb, 256>>>(e);
    // side stream: h_bondN_0 = relu(edge_attr[0:n] @ W_bond + b_bond)
    bond0_kernel<<<nwb, 256, 0, s1>>>(eattr, W_bond, b_bond, n);
    cudaEventRecord(evSide, s1);
    cudaStreamWaitEvent(0, evSide, 0);   // join: agg0 needs CSR + xproj + bond0

    // msg_0 (fused matvec over edges) and h_atom_1 = x_proj * msg_0
    agg0_kernel<<<nwb, 256>>>(eattr, W_bond, b_bond, n);

    for (int l = 0; l < 3; l++) {
        const float* Wl = W_seq + (size_t)l * 128 * 128;
        const float* bl = b_seq + (size_t)l * 128;
        // U = h_atom @ W_l ; V = h_bondN @ W_l  (one dual-source launch)
        gemm64_kernel<<<2 * g64, 128, G64_SMEM>>>(p_hatom, p_hbondN, Wl,
                                                  (const float*)0,
                                                  p_U, p_V, n, g64, 0);
        if (l < 2) {
            // bond_update runs on the side stream, concurrent with agg
            // (bond_update writes g_hbondN rows; agg writes g_hatom — disjoint)
            cudaEventRecord(evG[l], 0);
            cudaStreamWaitEvent(s1, evG[l], 0);
            bond_update_kernel<<<nwb, 256, 0, s1>>>(bl, n);
            cudaEventRecord(evBU[l], s1);
        }
        // msg: l<2 -> h_atom *= msg ; l==2 -> hfin = h_atom^2 * msg (into g_hbondN)
        agg_kernel<<<nwb, 256>>>(p_U, p_V, bl, n, (l == 2) ? 1 : 0);
        if (l < 2)
            cudaStreamWaitEvent(0, evBU[l], 0);  // next gemm needs h_bondN
    }

    // out = [hfin | x_proj] @ W_lin + b_lin
    gemm_out_kernel<<<g64, 128, GO_SMEM>>>(W_lin, b_lin, out, n);
}

// round 15
// speedup vs baseline: 1.1392x; 1.0451x over previous
#include <cuda_runtime.h>
#include <cstdint>

// ---------------------------------------------------------------------------
// CMPNN, restructured:
//   x_proj = relu(x @ W_atom + b)                         [N,128]
//   loop l=0..2:
//     msg[i] = sum_e m_e * max_e m_e ; h_atom *= msg
//     U = h_atom @ W_l ; V = h_bondN @ W_l                [N,128] each
//     h_bondN[v] = relu(U[iI[v]] - V[iJ[v]] + b_l)  (rows < N only)
//   final msg -> hfin = h_atom^2 * msg
//   out = [hfin | x_proj] @ W_lin + b_lin                 [N,64]
// GEMMs: scalar FFMA (R11 shape). Aggressive dual-stream schedule:
//   side stream: xproj, bond0, Vgemm_l, bond_update_l  (V double-buffered)
//   main stream: CSR build, agg0, Ugemm_l, agg_l, gemm_out
// The V-half of each layer's GEMM runs concurrently with the previous agg,
// leaving only U-GEMMs + aggs on the critical path.
// h_bond [E,128] is never materialized: m_e = relu(U[i_e]-V[j_e]+b).
// ---------------------------------------------------------------------------

#define NN_MAX 30000
#define EE_MAX 480000

__device__ int g_is64;
__device__ int g_idxI[EE_MAX];
__device__ int g_idxJ[EE_MAX];
__device__ int g_deg[NN_MAX];
__device__ int g_rowptr[NN_MAX + 1];
__device__ int g_cursor[NN_MAX];
__device__ int g_sortedJ[EE_MAX];
__device__ int g_sortedE[EE_MAX];

__device__ __align__(16) float g_xproj[NN_MAX * 128];
__device__ __align__(16) float g_hatom[NN_MAX * 128];
__device__ __align__(16) float g_hbondN[NN_MAX * 128];
__device__ __align__(16) float g_U[NN_MAX * 128];
__device__ __align__(16) float g_V[NN_MAX * 128];
__device__ __align__(16) float g_V2[NN_MAX * 128];

// ------------------------------- index setup -------------------------------

__global__ void init_kernel(const int* __restrict__ raw, int e, int n) {
    if (blockIdx.x == 0) {
        __shared__ int nz;
        if (threadIdx.x == 0) nz = 0;
        __syncthreads();
        int K = e < 2048 ? e : 2048;
        for (int t = threadIdx.x; t < K; t += blockDim.x)
            if (raw[2 * t + 1] != 0) nz = 1;
        __syncthreads();
        if (threadIdx.x == 0) g_is64 = (nz == 0) ? 1 : 0;
    }
    int t = blockIdx.x * blockDim.x + threadIdx.x;
    if (t < n) g_deg[t] = 0;
}

__global__ void convert_hist_kernel(const int* __restrict__ raw, int e) {
    int t = blockIdx.x * blockDim.x + threadIdx.x;
    if (t >= e) return;
    int i, j;
    if (g_is64) { i = raw[2 * t]; j = raw[2 * (e + t)]; }
    else        { i = raw[t];     j = raw[e + t]; }
    g_idxI[t] = i;
    g_idxJ[t] = j;
    atomicAdd(&g_deg[i], 1);
}

// Single-block exclusive scan, thread-coarsened + warp shuffles.
__global__ __launch_bounds__(1024) void scan_kernel(int n) {
    const int ITEMS = 32;                 // 1024*32 = 32768 >= NN_MAX
    __shared__ int wsum[32];
    int t = threadIdx.x;
    int base = t * ITEMS;
    int pre[ITEMS];
    int tot = 0;
#pragma unroll
    for (int i = 0; i < ITEMS; i++) {
        int idx = base + i;
        int d = (idx < n) ? g_deg[idx] : 0;
        pre[i] = tot;
        tot += d;
    }
    int lane = t & 31, wid = t >> 5;
    int incl = tot;
#pragma unroll
    for (int o = 1; o < 32; o <<= 1) {
        int v = __shfl_up_sync(0xffffffffu, incl, o);
        if (lane >= o) incl += v;
    }
    if (lane == 31) wsum[wid] = incl;
    __syncthreads();
    if (wid == 0) {
        int v = wsum[lane];
#pragma unroll
        for (int o = 1; o < 32; o <<= 1) {
            int u = __shfl_up_sync(0xffffffffu, v, o);
            if (lane >= o) v += u;
        }
        wsum[lane] = v;
    }
    __syncthreads();
    int warp_off = (wid > 0) ? wsum[wid - 1] : 0;
    int excl = warp_off + incl - tot;
#pragma unroll
    for (int i = 0; i < ITEMS; i++) {
        int idx = base + i;
        if (idx < n) {
            int p = excl + pre[i];
            g_rowptr[idx] = p;
            g_cursor[idx] = p;
        }
    }
    if (t == 1023) g_rowptr[n] = warp_off + incl;
}

__global__ void scatter_kernel(int e) {
    int t = blockIdx.x * blockDim.x + threadIdx.x;
    if (t >= e) return;
    int i = g_idxI[t];
    int p = atomicAdd(&g_cursor[i], 1);
    g_sortedJ[p] = g_idxJ[t];
    g_sortedE[p] = t;
}

// ------------------------------ 64-row SGEMM --------------------------------
// C[M,128] = act(A[M,128] @ W[128,128] + bias), BM=64 per CTA, 128 threads.
// Dual-source: blocks < nblk use (A1,C1), the rest (A2,C2).
// cp.async 2-stage pipeline over BK=32 chunks; conflict-free swizzled A.

#define G64_STG_A (64 * 32)                 // floats
#define G64_STG_B (32 * 128)                // floats
#define G64_STG   (G64_STG_A + G64_STG_B)   // 6144 floats = 24 KB
#define G64_SMEM  (2 * G64_STG * 4)         // 48 KB

__device__ __forceinline__ uint32_t smem_u32(const void* p) {
    uint32_t a;
    asm("{ .reg .u64 t; cvta.to.shared.u64 t, %1; cvt.u32.u64 %0, t; }"
        : "=r"(a) : "l"(p));
    return a;
}
__device__ __forceinline__ void cp16(uint32_t dst, const void* src) {
    asm volatile("cp.async.ca.shared.global [%0], [%1], 16;"
                 :: "r"(dst), "l"(src));
}

__global__ __launch_bounds__(128) void gemm64_kernel(
    const float* __restrict__ A1, const float* __restrict__ A2,
    const float* __restrict__ W, const float* __restrict__ bias,
    float* __restrict__ C1, float* __restrict__ C2,
    int M, int nblk, int act)
{
    extern __shared__ float sm[];
    uint32_t sbase = smem_u32(sm);

    const float* __restrict__ A;
    float* __restrict__ C;
    int bx = blockIdx.x;
    if (bx < nblk) { A = A1; C = C1; } else { A = A2; C = C2; bx -= nblk; }
    int row0 = bx * 64;
    int tid = threadIdx.x;
    int tx = tid & 15, ty = tid >> 4;

    auto load_chunk = [&](int c, int s) {
        uint32_t aBase = sbase + (uint32_t)(s * G64_STG) * 4u;
        uint32_t bBase = aBase + (uint32_t)G64_STG_A * 4u;
#pragma unroll
        for (int i = 0; i < 4; i++) {           // A: 64x32 fl = 512 f4
            int idx = tid + i * 128;
            int r = idx >> 3, q = idx & 7;
            int gr = row0 + r; if (gr > M - 1) gr = M - 1;   // tail rows discarded
            uint32_t dst = aBase + (uint32_t)(r * 32 + ((q ^ (r & 7)) << 2)) * 4u;
            cp16(dst, A + (size_t)gr * 128 + c * 32 + q * 4);
        }
#pragma unroll
        for (int i = 0; i < 8; i++) {           // B: 32x128 fl = 1024 f4
            int idx = tid + i * 128;
            int k = idx >> 5, q = idx & 31;
            uint32_t dst = bBase + (uint32_t)(k * 128 + q * 4) * 4u;
            cp16(dst, W + (size_t)(c * 32 + k) * 128 + q * 4);
        }
        asm volatile("cp.async.commit_group;");
    };

    float acc[8][8];
#pragma unroll
    for (int i = 0; i < 8; i++)
#pragma unroll
        for (int j = 0; j < 8; j++) acc[i][j] = 0.f;

    load_chunk(0, 0);

    for (int c = 0; c < 4; c++) {
        int s = c & 1;
        if (c < 3) {
            load_chunk(c + 1, s ^ 1);
            asm volatile("cp.async.wait_group 1;");
        } else {
            asm volatile("cp.async.wait_group 0;");
        }
        __syncthreads();
        const float* Asf = sm + s * G64_STG;
        const float* Bsf = Asf + G64_STG_A;
#pragma unroll 2
        for (int kq = 0; kq < 8; kq++) {        // k-quad: 4 k-steps
            float4 a4[8];
#pragma unroll
            for (int i = 0; i < 8; i++)
                a4[i] = *(const float4*)(Asf + (ty * 8 + i) * 32 + ((kq ^ i) << 2));
#pragma unroll
            for (int kk = 0; kk < 4; kk++) {
                int k = kq * 4 + kk;
                float4 b0 = *(const float4*)(Bsf + k * 128 + 4 * tx);
                float4 b1 = *(const float4*)(Bsf + k * 128 + 64 + 4 * tx);
                float a[8];
#pragma unroll
                for (int i = 0; i < 8; i++)
                    a[i] = (kk == 0) ? a4[i].x : (kk == 1) ? a4[i].y
                         : (kk == 2) ? a4[i].z : a4[i].w;
#pragma unroll
                for (int i = 0; i < 8; i++) {
                    acc[i][0] = fmaf(a[i], b0.x, acc[i][0]);
                    acc[i][1] = fmaf(a[i], b0.y, acc[i][1]);
                    acc[i][2] = fmaf(a[i], b0.z, acc[i][2]);
                    acc[i][3] = fmaf(a[i], b0.w, acc[i][3]);
                    acc[i][4] = fmaf(a[i], b1.x, acc[i][4]);
                    acc[i][5] = fmaf(a[i], b1.y, acc[i][5]);
                    acc[i][6] = fmaf(a[i], b1.z, acc[i][6]);
                    acc[i][7] = fmaf(a[i], b1.w, acc[i][7]);
                }
            }
        }
        __syncthreads();
    }

    float bb[8];
    if (bias) {
#pragma unroll
        for (int j = 0; j < 4; j++) { bb[j] = bias[4 * tx + j]; bb[4 + j] = bias[64 + 4 * tx + j]; }
    } else {
#pragma unroll
        for (int j = 0; j < 8; j++) bb[j] = 0.f;
    }
#pragma unroll
    for (int i = 0; i < 8; i++) {
        int r = row0 + ty * 8 + i;
        if (r < M) {
            float v[8];
#pragma unroll
            for (int j = 0; j < 8; j++) {
                float t = acc[i][j] + bb[j];
                v[j] = act ? fmaxf(t, 0.f) : t;
            }
            float* op = C + (size_t)r * 128;
            *(float4*)(op + 4 * tx)      = make_float4(v[0], v[1], v[2], v[3]);
            *(float4*)(op + 64 + 4 * tx) = make_float4(v[4], v[5], v[6], v[7]);
        }
    }
}

// -------------------------- out GEMM (BM=64, N=64) ---------------------------
// out[N,64] = [hfin | xproj] @ W_lin[256,64] + b_lin. K=256 in 8 chunks;
// chunks 0-3 read g_hbondN (hfin), 4-7 g_xproj. 128 threads, 8x4 acc.

#define GO_STG_A (64 * 32)
#define GO_STG_B (32 * 64)
#define GO_STG   (GO_STG_A + GO_STG_B)      // 4096 floats = 16 KB
#define GO_SMEM  (2 * GO_STG * 4)           // 32 KB

__global__ __launch_bounds__(128) void gemm_out_kernel(
    const float* __restrict__ Wlin, const float* __restrict__ blin,
    float* __restrict__ out, int M)
{
    extern __shared__ float sm[];
    uint32_t sbase = smem_u32(sm);
    int row0 = blockIdx.x * 64;
    int tid = threadIdx.x;
    int tx = tid & 15, ty = tid >> 4;

    auto load_chunk = [&](int c, int s) {
        const float* Asrc = (c < 4) ? g_hbondN : g_xproj;
        int kb = (c & 3) * 32;
        uint32_t aBase = sbase + (uint32_t)(s * GO_STG) * 4u;
        uint32_t bBase = aBase + (uint32_t)GO_STG_A * 4u;
#pragma unroll
        for (int i = 0; i < 4; i++) {           // A: 64x32 fl = 512 f4
            int idx = tid + i * 128;
            int r = idx >> 3, q = idx & 7;
            int gr = row0 + r; if (gr > M - 1) gr = M - 1;
            uint32_t dst = aBase + (uint32_t)(r * 32 + ((q ^ (r & 7)) << 2)) * 4u;
            cp16(dst, Asrc + (size_t)gr * 128 + kb + q * 4);
        }
#pragma unroll
        for (int i = 0; i < 4; i++) {           // B: 32x64 fl = 512 f4
            int idx = tid + i * 128;
            int k = idx >> 4, q = idx & 15;
            uint32_t dst = bBase + (uint32_t)(k * 64 + q * 4) * 4u;
            cp16(dst, Wlin + (size_t)(c * 32 + k) * 64 + q * 4);
        }
        asm volatile("cp.async.commit_group;");
    };

    float acc[8][4];
#pragma unroll
    for (int i = 0; i < 8; i++)
#pragma unroll
        for (int j = 0; j < 4; j++) acc[i][j] = 0.f;

    load_chunk(0, 0);

    for (int c = 0; c < 8; c++) {
        int s = c & 1;
        if (c < 7) {
            load_chunk(c + 1, s ^ 1);
            asm volatile("cp.async.wait_group 1;");
        } else {
            asm volatile("cp.async.wait_group 0;");
        }
        __syncthreads();
        const float* Asf = sm + s * GO_STG;
        const float* Bsf = Asf + GO_STG_A;
#pragma unroll 2
        for (int kq = 0; kq < 8; kq++) {
            float4 a4[8];
#pragma unroll
            for (int i = 0; i < 8; i++) {
                int r = ty * 8 + i;
                a4[i] = *(const float4*)(Asf + r * 32 + ((kq ^ (r & 7)) << 2));
            }
#pragma unroll
            for (int kk = 0; kk < 4; kk++) {
                int k = kq * 4 + kk;
                float4 b0 = *(const float4*)(Bsf + k * 64 + 4 * tx);
                float a[8];
#pragma unroll
                for (int i = 0; i < 8; i++)
                    a[i] = (kk == 0) ? a4[i].x : (kk == 1) ? a4[i].y
                         : (kk == 2) ? a4[i].z : a4[i].w;
#pragma unroll
                for (int i = 0; i < 8; i++) {
                    acc[i][0] = fmaf(a[i], b0.x, acc[i][0]);
                    acc[i][1] = fmaf(a[i], b0.y, acc[i][1]);
                    acc[i][2] = fmaf(a[i], b0.z, acc[i][2]);
                    acc[i][3] = fmaf(a[i], b0.w, acc[i][3]);
                }
            }
        }
        __syncthreads();
    }

    float bb[4] = {blin[4 * tx], blin[4 * tx + 1], blin[4 * tx + 2], blin[4 * tx + 3]};
#pragma unroll
    for (int i = 0; i < 8; i++) {
        int r = row0 + ty * 8 + i;
        if (r < M) {
            *(float4*)(out + (size_t)r * 64 + 4 * tx) =
                make_float4(acc[i][0] + bb[0], acc[i][1] + bb[1],
                            acc[i][2] + bb[2], acc[i][3] + bb[3]);
        }
    }
}

// ------------------------- per-edge helpers / agg ---------------------------

__device__ __forceinline__ void agg_step(const float4& u, const float4& b,
                                         const float4& v, float4& s, float4& mx) {
    float m0 = fmaxf(u.x - v.x + b.x, 0.f);
    float m1 = fmaxf(u.y - v.y + b.y, 0.f);
    float m2 = fmaxf(u.z - v.z + b.z, 0.f);
    float m3 = fmaxf(u.w - v.w + b.w, 0.f);
    s.x += m0; s.y += m1; s.z += m2; s.w += m3;
    mx.x = fmaxf(mx.x, m0); mx.y = fmaxf(mx.y, m1);
    mx.z = fmaxf(mx.z, m2); mx.w = fmaxf(mx.w, m3);
}

__global__ __launch_bounds__(256) void agg_kernel(
    const float* __restrict__ U, const float* __restrict__ V,
    const float* __restrict__ bias, int n, int final_mode)
{
    int gw = (blockIdx.x * blockDim.x + threadIdx.x) >> 5;
    int lane = threadIdx.x & 31;
    if (gw >= n) return;
    int start = g_rowptr[gw], end = g_rowptr[gw + 1];
    float4 u = *(const float4*)(U + (size_t)gw * 128 + lane * 4);
    float4 b = *(const float4*)(bias + lane * 4);
    float4 s  = make_float4(0.f, 0.f, 0.f, 0.f);
    float4 mx = make_float4(0.f, 0.f, 0.f, 0.f);
    for (int c = start; c < end; c += 32) {
        int cnt = end - c; if (cnt > 32) cnt = 32;
        int myj = g_sortedJ[c + (lane < cnt ? lane : 0)];
        int t = 0;
        for (; t + 4 <= cnt; t += 4) {
            int j0 = __shfl_sync(0xffffffffu, myj, t);
            int j1 = __shfl_sync(0xffffffffu, myj, t + 1);
            int j2 = __shfl_sync(0xffffffffu, myj, t + 2);
            int j3 = __shfl_sync(0xffffffffu, myj, t + 3);
            float4 v0 = *(const float4*)(V + (size_t)j0 * 128 + lane * 4);
            float4 v1 = *(const float4*)(V + (size_t)j1 * 128 + lane * 4);
            float4 v2 = *(const float4*)(V + (size_t)j2 * 128 + lane * 4);
            float4 v3 = *(const float4*)(V + (size_t)j3 * 128 + lane * 4);
            agg_step(u, b, v0, s, mx);
            agg_step(u, b, v1, s, mx);
            agg_step(u, b, v2, s, mx);
            agg_step(u, b, v3, s, mx);
        }
        for (; t < cnt; t++) {
            int j0 = __shfl_sync(0xffffffffu, myj, t);
            float4 v0 = *(const float4*)(V + (size_t)j0 * 128 + lane * 4);
            agg_step(u, b, v0, s, mx);
        }
    }
    float4 msg = make_float4(s.x * mx.x, s.y * mx.y, s.z * mx.z, s.w * mx.w);
    float* hp = g_hatom + (size_t)gw * 128 + lane * 4;
    float4 h = *(float4*)hp;
    if (!final_mode) {
        h.x *= msg.x; h.y *= msg.y; h.z *= msg.z; h.w *= msg.w;
        *(float4*)hp = h;
    } else {
        float4 o = make_float4(h.x * h.x * msg.x, h.y * h.y * msg.y,
                               h.z * h.z * msg.z, h.w * h.w * msg.w);
        *(float4*)(g_hbondN + (size_t)gw * 128 + lane * 4) = o;
    }
}

__global__ __launch_bounds__(256) void agg0_kernel(
    const float* __restrict__ eattr, const float* __restrict__ Wb,
    const float* __restrict__ bb, int n)
{
    __shared__ float Wbs[16][128];
    for (int i = threadIdx.x; i < 512; i += 256)
        ((float4*)Wbs)[i] = ((const float4*)Wb)[i];
    __syncthreads();
    int gw = (blockIdx.x * blockDim.x + threadIdx.x) >> 5;
    int lane = threadIdx.x & 31;
    if (gw >= n) return;
    int start = g_rowptr[gw], end = g_rowptr[gw + 1];
    float4 b = *(const float4*)(bb + lane * 4);
    float4 s  = make_float4(0.f, 0.f, 0.f, 0.f);
    float4 mx = make_float4(0.f, 0.f, 0.f, 0.f);
    for (int c = start; c < end; c += 32) {
        int cnt = end - c; if (cnt > 32) cnt = 32;
        int myE = g_sortedE[c + (lane < cnt ? lane : 0)];
        for (int t = 0; t < cnt; t++) {
            int eid = __shfl_sync(0xffffffffu, myE, t);
            const float4* ea = (const float4*)(eattr + (size_t)eid * 16);
            float ec[16];
            *(float4*)(&ec[0])  = ea[0];
            *(float4*)(&ec[4])  = ea[1];
            *(float4*)(&ec[8])  = ea[2];
            *(float4*)(&ec[12]) = ea[3];
            float4 m = b;
#pragma unroll
            for (int q = 0; q < 16; q++) {
                float4 w = *(const float4*)(&Wbs[q][lane * 4]);
                m.x = fmaf(ec[q], w.x, m.x);
                m.y = fmaf(ec[q], w.y, m.y);
                m.z = fmaf(ec[q], w.z, m.z);
                m.w = fmaf(ec[q], w.w, m.w);
            }
            m.x = fmaxf(m.x, 0.f); m.y = fmaxf(m.y, 0.f);
            m.z = fmaxf(m.z, 0.f); m.w = fmaxf(m.w, 0.f);
            s.x += m.x; s.y += m.y; s.z += m.z; s.w += m.w;
            mx.x = fmaxf(mx.x, m.x); mx.y = fmaxf(mx.y, m.y);
            mx.z = fmaxf(mx.z, m.z); mx.w = fmaxf(mx.w, m.w);
        }
    }
    float4 xp = *(const float4*)(g_xproj + (size_t)gw * 128 + lane * 4);
    float4 o = make_float4(xp.x * s.x * mx.x, xp.y * s.y * mx.y,
                           xp.z * s.z * mx.z, xp.w * s.w * mx.w);
    *(float4*)(g_hatom + (size_t)gw * 128 + lane * 4) = o;
}

__global__ __launch_bounds__(256) void bond0_kernel(
    const float* __restrict__ eattr, const float* __restrict__ Wb,
    const float* __restrict__ bb, int n)
{
    __shared__ float Wbs[16][128];
    for (int i = threadIdx.x; i < 512; i += 256)
        ((float4*)Wbs)[i] = ((const float4*)Wb)[i];
    __syncthreads();
    int v = (blockIdx.x * blockDim.x + threadIdx.x) >> 5;
    int lane = threadIdx.x & 31;
    if (v >= n) return;
    float4 m = *(const float4*)(bb + lane * 4);
    const float4* ea = (const float4*)(eattr + (size_t)v * 16);
    float ec[16];
    *(float4*)(&ec[0])  = ea[0];
    *(float4*)(&ec[4])  = ea[1];
    *(float4*)(&ec[8])  = ea[2];
    *(float4*)(&ec[12]) = ea[3];
#pragma unroll
    for (int q = 0; q < 16; q++) {
        float4 w = *(const float4*)(&Wbs[q][lane * 4]);
        m.x = fmaf(ec[q], w.x, m.x);
        m.y = fmaf(ec[q], w.y, m.y);
        m.z = fmaf(ec[q], w.z, m.z);
        m.w = fmaf(ec[q], w.w, m.w);
    }
    m.x = fmaxf(m.x, 0.f); m.y = fmaxf(m.y, 0.f);
    m.z = fmaxf(m.z, 0.f); m.w = fmaxf(m.w, 0.f);
    *(float4*)(g_hbondN + (size_t)v * 128 + lane * 4) = m;
}

// h_bondN[v] = relu(U[idxI[v]] - V[idxJ[v]] + b), v < N (edge ids 0..N-1).
__global__ __launch_bounds__(256) void bond_update_kernel(
    const float* __restrict__ V, const float* __restrict__ bias, int n)
{
    int v = (blockIdx.x * blockDim.x + threadIdx.x) >> 5;
    int lane = threadIdx.x & 31;
    if (v >= n) return;
    int i = g_idxI[v], j = g_idxJ[v];
    float4 u  = *(const float4*)(g_U + (size_t)i * 128 + lane * 4);
    float4 vv = *(const float4*)(V + (size_t)j * 128 + lane * 4);
    float4 b  = *(const float4*)(bias + lane * 4);
    float4 o = make_float4(fmaxf(u.x - vv.x + b.x, 0.f),
                           fmaxf(u.y - vv.y + b.y, 0.f),
                           fmaxf(u.z - vv.z + b.z, 0.f),
                           fmaxf(u.w - vv.w + b.w, 0.f));
    *(float4*)(g_hbondN + (size_t)v * 128 + lane * 4) = o;
}

// --------------------------------- launch -----------------------------------

extern "C" void kernel_launch(void* const* d_in, const int* in_sizes, int n_in,
                              void* d_out, int out_size) {
    const float* x      = (const float*)d_in[0];
    const int*   eraw   = (const int*)d_in[1];
    const float* eattr  = (const float*)d_in[2];
    const float* W_atom = (const float*)d_in[3];
    const float* b_atom = (const float*)d_in[4];
    const float* W_bond = (const float*)d_in[5];
    const float* b_bond = (const float*)d_in[6];
    const float* W_seq  = (const float*)d_in[7];
    const float* b_seq  = (const float*)d_in[8];
    const float* W_lin  = (const float*)d_in[9];
    const float* b_lin  = (const float*)d_in[10];
    float* out = (float*)d_out;

    int n = in_sizes[0] / 128;   // 30000
    int e = in_sizes[2] / 16;    // 480000
    if (n > NN_MAX) n = NN_MAX;
    if (e > EE_MAX) e = EE_MAX;

    float *p_xproj, *p_hatom, *p_hbondN, *p_U, *p_V, *p_V2;
    cudaGetSymbolAddress((void**)&p_xproj,  g_xproj);
    cudaGetSymbolAddress((void**)&p_hatom,  g_hatom);
    cudaGetSymbolAddress((void**)&p_hbondN, g_hbondN);
    cudaGetSymbolAddress((void**)&p_U,      g_U);
    cudaGetSymbolAddress((void**)&p_V,      g_V);
    cudaGetSymbolAddress((void**)&p_V2,     g_V2);

    static cudaStream_t s1 = 0;
    static cudaEvent_t evFork, evXP, evU0, evU1, evV0, evV1, evV2;
    static int inited = 0;
    if (!inited) {
        cudaFuncSetAttribute(gemm64_kernel,
                             cudaFuncAttributeMaxDynamicSharedMemorySize, G64_SMEM);
        cudaFuncSetAttribute(gemm_out_kernel,
                             cudaFuncAttributeMaxDynamicSharedMemorySize, GO_SMEM);
        cudaStreamCreateWithFlags(&s1, cudaStreamNonBlocking);
        cudaEventCreateWithFlags(&evFork, cudaEventDisableTiming);
        cudaEventCreateWithFlags(&evXP,   cudaEventDisableTiming);
        cudaEventCreateWithFlags(&evU0,   cudaEventDisableTiming);
        cudaEventCreateWithFlags(&evU1,   cudaEventDisableTiming);
        cudaEventCreateWithFlags(&evV0,   cudaEventDisableTiming);
        cudaEventCreateWithFlags(&evV1,   cudaEventDisableTiming);
        cudaEventCreateWithFlags(&evV2,   cudaEventDisableTiming);
        inited = 1;
    }
    cudaEvent_t evU[2] = {evU0, evU1};
    cudaEvent_t evV[3] = {evV0, evV1, evV2};
    float* Vbuf[3] = {p_V, p_V2, p_V};   // per-layer V buffer (ping-pong)

    int eb  = (e + 255) / 256;
    int nb  = (n + 255) / 256;
    int nwb = (n * 32 + 255) / 256;     // warp-per-node grids
    int g64 = (n + 63) / 64;            // BM=64 GEMM row blocks

    // Fork: side stream is independent of the CSR build.
    cudaEventRecord(evFork, 0);
    cudaStreamWaitEvent(s1, evFork, 0);

    // main: CSR build
    init_kernel<<<nb, 256>>>(eraw, e, n);
    convert_hist_kernel<<<eb, 256>>>(eraw, e);
    // side: x_proj = relu(x @ W_atom + b_atom)   (4th launch = ncu slot)
    gemm64_kernel<<<g64, 128, G64_SMEM, s1>>>(x, x, W_atom, b_atom,
                                              p_xproj, p_xproj, n, g64, 1);
    cudaEventRecord(evXP, s1);
    scan_kernel<<<1, 1024>>>(n);
    scatter_kernel<<<eb, 256>>>(e);
    // side: h_bondN_0 = relu(edge_attr[0:n] @ W_bond + b_bond), then
    //       V_0 = h_bondN_0 @ W_0  (concurrent with agg0 on main)
    bond0_kernel<<<nwb, 256, 0, s1>>>(eattr, W_bond, b_bond, n);
    gemm64_kernel<<<g64, 128, G64_SMEM, s1>>>(p_hbondN, p_hbondN,
                                              W_seq, (const float*)0,
                                              Vbuf[0], Vbuf[0], n, g64, 0);
    cudaEventRecord(evV[0], s1);

    // main: agg0 needs CSR + xproj (NOT bond0)
    cudaStreamWaitEvent(0, evXP, 0);
    agg0_kernel<<<nwb, 256>>>(eattr, W_bond, b_bond, n);

    for (int l = 0; l < 3; l++) {
        const float* Wl = W_seq + (size_t)l * 128 * 128;
        const float* bl = b_seq + (size_t)l * 128;
        // main: U_l = h_atom @ W_l
        gemm64_kernel<<<g64, 128, G64_SMEM>>>(p_hatom, p_hatom, Wl,
                                              (const float*)0,
                                              p_U, p_U, n, g64, 0);
        if (l < 2) {
            // side: bond_update_l (needs U_l + V_l), then V_{l+1} GEMM —
            // both run concurrent with main's agg_l.
            cudaEventRecord(evU[l], 0);
            cudaStreamWaitEvent(s1, evU[l], 0);
            bond_update_kernel<<<nwb, 256, 0, s1>>>(Vbuf[l], bl, n);
            const float* Wn = W_seq + (size_t)(l + 1) * 128 * 128;
            gemm64_kernel<<<g64, 128, G64_SMEM, s1>>>(p_hbondN, p_hbondN, Wn,
                                                      (const float*)0,
                                                      Vbuf[l + 1], Vbuf[l + 1],
                                                      n, g64, 0);
            cudaEventRecord(evV[l + 1], s1);
        }
        // main: agg_l needs U_l (in-stream) + V_l (side)
        cudaStreamWaitEvent(0, evV[l], 0);
        agg_kernel<<<nwb, 256>>>(p_U, Vbuf[l], bl, n, (l == 2) ? 1 : 0);
    }

    // out = [hfin | x_proj] @ W_lin + b_lin
    gemm_out_kernel<<<g64, 128, GO_SMEM>>>(W_lin, b_lin, out, n);
}

// round 16
// speedup vs baseline: 1.1820x; 1.0375x over previous
#include <cuda_runtime.h>
#include <cstdint>

// ---------------------------------------------------------------------------
// CMPNN, restructured:
//   x_proj = relu(x @ W_atom + b)                         [N,128]
//   loop l=0..2:
//     msg[i] = sum_e m_e * max_e m_e ; h_atom *= msg
//     U = h_atom @ W_l ; V = h_bondN @ W_l                [N,128] each
//     h_bondN[v] = relu(U[iI[v]] - V[iJ[v]] + b_l)  (rows < N only)
//   final msg -> hfin = h_atom^2 * msg
//   out = [hfin | x_proj] @ W_lin + b_lin                 [N,64]
// GEMMs: scalar FFMA (R11 shape). Dual-stream schedule:
//   side stream: xproj, bond0, Vgemm_l, bond_update_l  (V double-buffered)
//   main stream: CSR build, agg0, Ugemm_l, agg_l, gemm_out
// Scan rewritten with coalesced loads/stores (warp-chunk ownership + shuffle
// scans) — the old per-thread-contiguous layout cost 51 us in sector replays.
// h_bond [E,128] is never materialized: m_e = relu(U[i_e]-V[j_e]+b).
// ---------------------------------------------------------------------------

#define NN_MAX 30000
#define EE_MAX 480000

__device__ int g_is64;
__device__ int g_idxI[EE_MAX];
__device__ int g_idxJ[EE_MAX];
__device__ int g_deg[NN_MAX];
__device__ int g_rowptr[NN_MAX + 1];
__device__ int g_cursor[NN_MAX];
__device__ int g_sortedJ[EE_MAX];
__device__ int g_sortedE[EE_MAX];

__device__ __align__(16) float g_xproj[NN_MAX * 128];
__device__ __align__(16) float g_hatom[NN_MAX * 128];
__device__ __align__(16) float g_hbondN[NN_MAX * 128];
__device__ __align__(16) float g_U[NN_MAX * 128];
__device__ __align__(16) float g_V[NN_MAX * 128];
__device__ __align__(16) float g_V2[NN_MAX * 128];

// ------------------------------- index setup -------------------------------

__global__ void init_kernel(const int* __restrict__ raw, int e, int n) {
    if (blockIdx.x == 0) {
        __shared__ int nz;
        if (threadIdx.x == 0) nz = 0;
        __syncthreads();
        int K = e < 2048 ? e : 2048;
        for (int t = threadIdx.x; t < K; t += blockDim.x)
            if (raw[2 * t + 1] != 0) nz = 1;
        __syncthreads();
        if (threadIdx.x == 0) g_is64 = (nz == 0) ? 1 : 0;
    }
    int t = blockIdx.x * blockDim.x + threadIdx.x;
    if (t < n) g_deg[t] = 0;
}

__global__ void convert_hist_kernel(const int* __restrict__ raw, int e) {
    int t = blockIdx.x * blockDim.x + threadIdx.x;
    if (t >= e) return;
    int i, j;
    if (g_is64) { i = raw[2 * t]; j = raw[2 * (e + t)]; }
    else        { i = raw[t];     j = raw[e + t]; }
    g_idxI[t] = i;
    g_idxJ[t] = j;
    atomicAdd(&g_deg[i], 1);
}

// Single-block exclusive scan, fully coalesced:
// warp w owns items [w*1024, w*1024+1024); lane l holds items w*1024+i*32+l.
// Per row i: warp shuffle-scan gives lane-exclusive prefix + row total;
// a running row-total gives the in-chunk offset; warp0 scans warp totals.
__global__ __launch_bounds__(1024) void scan_kernel(int n) {
    __shared__ int wsum[32];
    int tid = threadIdx.x;
    int lane = tid & 31, w = tid >> 5;
    int base = w * 1024;                  // 32 warps * 1024 = 32768 >= NN_MAX
    int d[32], pre[32];
#pragma unroll
    for (int i = 0; i < 32; i++) {
        int idx = base + i * 32 + lane;   // coalesced
        d[i] = (idx < n) ? g_deg[idx] : 0;
    }
    int running = 0;
#pragma unroll
    for (int i = 0; i < 32; i++) {
        int incl = d[i];
#pragma unroll
        for (int o = 1; o < 32; o <<= 1) {
            int v = __shfl_up_sync(0xffffffffu, incl, o);
            if (lane >= o) incl += v;
        }
        pre[i] = running + incl - d[i];   // exclusive within chunk
        running += __shfl_sync(0xffffffffu, incl, 31);
    }
    if (lane == 31) wsum[w] = running;
    __syncthreads();
    if (w == 0) {
        int v = wsum[lane];
#pragma unroll
        for (int o = 1; o < 32; o <<= 1) {
            int u = __shfl_up_sync(0xffffffffu, v, o);
            if (lane >= o) v += u;
        }
        wsum[lane] = v;                   // inclusive warp totals
    }
    __syncthreads();
    int off = (w > 0) ? wsum[w - 1] : 0;
#pragma unroll
    for (int i = 0; i < 32; i++) {
        int idx = base + i * 32 + lane;   // coalesced
        if (idx < n) {
            int p = off + pre[i];
            g_rowptr[idx] = p;
            g_cursor[idx] = p;
        }
    }
    if (tid == 1023) g_rowptr[n] = wsum[31];
}

__global__ void scatter_kernel(int e) {
    int t = blockIdx.x * blockDim.x + threadIdx.x;
    if (t >= e) return;
    int i = g_idxI[t];
    int p = atomicAdd(&g_cursor[i], 1);
    g_sortedJ[p] = g_idxJ[t];
    g_sortedE[p] = t;
}

// ------------------------------ 64-row SGEMM --------------------------------
// C[M,128] = act(A[M,128] @ W[128,128] + bias), BM=64 per CTA, 128 threads.
// Dual-source: blocks < nblk use (A1,C1), the rest (A2,C2).
// cp.async 2-stage pipeline over BK=32 chunks; conflict-free swizzled A.

#define G64_STG_A (64 * 32)                 // floats
#define G64_STG_B (32 * 128)                // floats
#define G64_STG   (G64_STG_A + G64_STG_B)   // 6144 floats = 24 KB
#define G64_SMEM  (2 * G64_STG * 4)         // 48 KB

__device__ __forceinline__ uint32_t smem_u32(const void* p) {
    uint32_t a;
    asm("{ .reg .u64 t; cvta.to.shared.u64 t, %1; cvt.u32.u64 %0, t; }"
        : "=r"(a) : "l"(p));
    return a;
}
__device__ __forceinline__ void cp16(uint32_t dst, const void* src) {
    asm volatile("cp.async.ca.shared.global [%0], [%1], 16;"
                 :: "r"(dst), "l"(src));
}

__global__ __launch_bounds__(128) void gemm64_kernel(
    const float* __restrict__ A1, const float* __restrict__ A2,
    const float* __restrict__ W, const float* __restrict__ bias,
    float* __restrict__ C1, float* __restrict__ C2,
    int M, int nblk, int act)
{
    extern __shared__ float sm[];
    uint32_t sbase = smem_u32(sm);

    const float* __restrict__ A;
    float* __restrict__ C;
    int bx = blockIdx.x;
    if (bx < nblk) { A = A1; C = C1; } else { A = A2; C = C2; bx -= nblk; }
    int row0 = bx * 64;
    int tid = threadIdx.x;
    int tx = tid & 15, ty = tid >> 4;

    auto load_chunk = [&](int c, int s) {
        uint32_t aBase = sbase + (uint32_t)(s * G64_STG) * 4u;
        uint32_t bBase = aBase + (uint32_t)G64_STG_A * 4u;
#pragma unroll
        for (int i = 0; i < 4; i++) {           // A: 64x32 fl = 512 f4
            int idx = tid + i * 128;
            int r = idx >> 3, q = idx & 7;
            int gr = row0 + r; if (gr > M - 1) gr = M - 1;   // tail rows discarded
            uint32_t dst = aBase + (uint32_t)(r * 32 + ((q ^ (r & 7)) << 2)) * 4u;
            cp16(dst, A + (size_t)gr * 128 + c * 32 + q * 4);
        }
#pragma unroll
        for (int i = 0; i < 8; i++) {           // B: 32x128 fl = 1024 f4
            int idx = tid + i * 128;
            int k = idx >> 5, q = idx & 31;
            uint32_t dst = bBase + (uint32_t)(k * 128 + q * 4) * 4u;
            cp16(dst, W + (size_t)(c * 32 + k) * 128 + q * 4);
        }
        asm volatile("cp.async.commit_group;");
    };

    float acc[8][8];
#pragma unroll
    for (int i = 0; i < 8; i++)
#pragma unroll
        for (int j = 0; j < 8; j++) acc[i][j] = 0.f;

    load_chunk(0, 0);

    for (int c = 0; c < 4; c++) {
        int s = c & 1;
        if (c < 3) {
            load_chunk(c + 1, s ^ 1);
            asm volatile("cp.async.wait_group 1;");
        } else {
            asm volatile("cp.async.wait_group 0;");
        }
        __syncthreads();
        const float* Asf = sm + s * G64_STG;
        const float* Bsf = Asf + G64_STG_A;
#pragma unroll 2
        for (int kq = 0; kq < 8; kq++) {        // k-quad: 4 k-steps
            float4 a4[8];
#pragma unroll
            for (int i = 0; i < 8; i++)
                a4[i] = *(const float4*)(Asf + (ty * 8 + i) * 32 + ((kq ^ i) << 2));
#pragma unroll
            for (int kk = 0; kk < 4; kk++) {
                int k = kq * 4 + kk;
                float4 b0 = *(const float4*)(Bsf + k * 128 + 4 * tx);
                float4 b1 = *(const float4*)(Bsf + k * 128 + 64 + 4 * tx);
                float a[8];
#pragma unroll
                for (int i = 0; i < 8; i++)
                    a[i] = (kk == 0) ? a4[i].x : (kk == 1) ? a4[i].y
                         : (kk == 2) ? a4[i].z : a4[i].w;
#pragma unroll
                for (int i = 0; i < 8; i++) {
                    acc[i][0] = fmaf(a[i], b0.x, acc[i][0]);
                    acc[i][1] = fmaf(a[i], b0.y, acc[i][1]);
                    acc[i][2] = fmaf(a[i], b0.z, acc[i][2]);
                    acc[i][3] = fmaf(a[i], b0.w, acc[i][3]);
                    acc[i][4] = fmaf(a[i], b1.x, acc[i][4]);
                    acc[i][5] = fmaf(a[i], b1.y, acc[i][5]);
                    acc[i][6] = fmaf(a[i], b1.z, acc[i][6]);
                    acc[i][7] = fmaf(a[i], b1.w, acc[i][7]);
                }
            }
        }
        __syncthreads();
    }

    float bb[8];
    if (bias) {
#pragma unroll
        for (int j = 0; j < 4; j++) { bb[j] = bias[4 * tx + j]; bb[4 + j] = bias[64 + 4 * tx + j]; }
    } else {
#pragma unroll
        for (int j = 0; j < 8; j++) bb[j] = 0.f;
    }
#pragma unroll
    for (int i = 0; i < 8; i++) {
        int r = row0 + ty * 8 + i;
        if (r < M) {
            float v[8];
#pragma unroll
            for (int j = 0; j < 8; j++) {
                float t = acc[i][j] + bb[j];
                v[j] = act ? fmaxf(t, 0.f) : t;
            }
            float* op = C + (size_t)r * 128;
            *(float4*)(op + 4 * tx)      = make_float4(v[0], v[1], v[2], v[3]);
            *(float4*)(op + 64 + 4 * tx) = make_float4(v[4], v[5], v[6], v[7]);
        }
    }
}

// -------------------------- out GEMM (BM=64, N=64) ---------------------------
// out[N,64] = [hfin | xproj] @ W_lin[256,64] + b_lin. K=256 in 8 chunks;
// chunks 0-3 read g_hbondN (hfin), 4-7 g_xproj. 128 threads, 8x4 acc.

#define GO_STG_A (64 * 32)
#define GO_STG_B (32 * 64)
#define GO_STG   (GO_STG_A + GO_STG_B)      // 4096 floats = 16 KB
#define GO_SMEM  (2 * GO_STG * 4)           // 32 KB

__global__ __launch_bounds__(128) void gemm_out_kernel(
    const float* __restrict__ Wlin, const float* __restrict__ blin,
    float* __restrict__ out, int M)
{
    extern __shared__ float sm[];
    uint32_t sbase = smem_u32(sm);
    int row0 = blockIdx.x * 64;
    int tid = threadIdx.x;
    int tx = tid & 15, ty = tid >> 4;

    auto load_chunk = [&](int c, int s) {
        const float* Asrc = (c < 4) ? g_hbondN : g_xproj;
        int kb = (c & 3) * 32;
        uint32_t aBase = sbase + (uint32_t)(s * GO_STG) * 4u;
        uint32_t bBase = aBase + (uint32_t)GO_STG_A * 4u;
#pragma unroll
        for (int i = 0; i < 4; i++) {           // A: 64x32 fl = 512 f4
            int idx = tid + i * 128;
            int r = idx >> 3, q = idx & 7;
            int gr = row0 + r; if (gr > M - 1) gr = M - 1;
            uint32_t dst = aBase + (uint32_t)(r * 32 + ((q ^ (r & 7)) << 2)) * 4u;
            cp16(dst, Asrc + (size_t)gr * 128 + kb + q * 4);
        }
#pragma unroll
        for (int i = 0; i < 4; i++) {           // B: 32x64 fl = 512 f4
            int idx = tid + i * 128;
            int k = idx >> 4, q = idx & 15;
            uint32_t dst = bBase + (uint32_t)(k * 64 + q * 4) * 4u;
            cp16(dst, Wlin + (size_t)(c * 32 + k) * 64 + q * 4);
        }
        asm volatile("cp.async.commit_group;");
    };

    float acc[8][4];
#pragma unroll
    for (int i = 0; i < 8; i++)
#pragma unroll
        for (int j = 0; j < 4; j++) acc[i][j] = 0.f;

    load_chunk(0, 0);

    for (int c = 0; c < 8; c++) {
        int s = c & 1;
        if (c < 7) {
            load_chunk(c + 1, s ^ 1);
            asm volatile("cp.async.wait_group 1;");
        } else {
            asm volatile("cp.async.wait_group 0;");
        }
        __syncthreads();
        const float* Asf = sm + s * GO_STG;
        const float* Bsf = Asf + GO_STG_A;
#pragma unroll 2
        for (int kq = 0; kq < 8; kq++) {
            float4 a4[8];
#pragma unroll
            for (int i = 0; i < 8; i++) {
                int r = ty * 8 + i;
                a4[i] = *(const float4*)(Asf + r * 32 + ((kq ^ (r & 7)) << 2));
            }
#pragma unroll
            for (int kk = 0; kk < 4; kk++) {
                int k = kq * 4 + kk;
                float4 b0 = *(const float4*)(Bsf + k * 64 + 4 * tx);
                float a[8];
#pragma unroll
                for (int i = 0; i < 8; i++)
                    a[i] = (kk == 0) ? a4[i].x : (kk == 1) ? a4[i].y
                         : (kk == 2) ? a4[i].z : a4[i].w;
#pragma unroll
                for (int i = 0; i < 8; i++) {
                    acc[i][0] = fmaf(a[i], b0.x, acc[i][0]);
                    acc[i][1] = fmaf(a[i], b0.y, acc[i][1]);
                    acc[i][2] = fmaf(a[i], b0.z, acc[i][2]);
                    acc[i][3] = fmaf(a[i], b0.w, acc[i][3]);
                }
            }
        }
        __syncthreads();
    }

    float bb[4] = {blin[4 * tx], blin[4 * tx + 1], blin[4 * tx + 2], blin[4 * tx + 3]};
#pragma unroll
    for (int i = 0; i < 8; i++) {
        int r = row0 + ty * 8 + i;
        if (r < M) {
            *(float4*)(out + (size_t)r * 64 + 4 * tx) =
                make_float4(acc[i][0] + bb[0], acc[i][1] + bb[1],
                            acc[i][2] + bb[2], acc[i][3] + bb[3]);
        }
    }
}

// ------------------------- per-edge helpers / agg ---------------------------

__device__ __forceinline__ void agg_step(const float4& u, const float4& b,
                                         const float4& v, float4& s, float4& mx) {
    float m0 = fmaxf(u.x - v.x + b.x, 0.f);
    float m1 = fmaxf(u.y - v.y + b.y, 0.f);
    float m2 = fmaxf(u.z - v.z + b.z, 0.f);
    float m3 = fmaxf(u.w - v.w + b.w, 0.f);
    s.x += m0; s.y += m1; s.z += m2; s.w += m3;
    mx.x = fmaxf(mx.x, m0); mx.y = fmaxf(mx.y, m1);
    mx.z = fmaxf(mx.z, m2); mx.w = fmaxf(mx.w, m3);
}

__global__ __launch_bounds__(256) void agg_kernel(
    const float* __restrict__ U, const float* __restrict__ V,
    const float* __restrict__ bias, int n, int final_mode)
{
    int gw = (blockIdx.x * blockDim.x + threadIdx.x) >> 5;
    int lane = threadIdx.x & 31;
    if (gw >= n) return;
    int start = g_rowptr[gw], end = g_rowptr[gw + 1];
    float4 u = *(const float4*)(U + (size_t)gw * 128 + lane * 4);
    float4 b = *(const float4*)(bias + lane * 4);
    float4 s  = make_float4(0.f, 0.f, 0.f, 0.f);
    float4 mx = make_float4(0.f, 0.f, 0.f, 0.f);
    for (int c = start; c < end; c += 32) {
        int cnt = end - c; if (cnt > 32) cnt = 32;
        int myj = g_sortedJ[c + (lane < cnt ? lane : 0)];
        int t = 0;
        for (; t + 4 <= cnt; t += 4) {
            int j0 = __shfl_sync(0xffffffffu, myj, t);
            int j1 = __shfl_sync(0xffffffffu, myj, t + 1);
            int j2 = __shfl_sync(0xffffffffu, myj, t + 2);
            int j3 = __shfl_sync(0xffffffffu, myj, t + 3);
            float4 v0 = *(const float4*)(V + (size_t)j0 * 128 + lane * 4);
            float4 v1 = *(const float4*)(V + (size_t)j1 * 128 + lane * 4);
            float4 v2 = *(const float4*)(V + (size_t)j2 * 128 + lane * 4);
            float4 v3 = *(const float4*)(V + (size_t)j3 * 128 + lane * 4);
            agg_step(u, b, v0, s, mx);
            agg_step(u, b, v1, s, mx);
            agg_step(u, b, v2, s, mx);
            agg_step(u, b, v3, s, mx);
        }
        for (; t < cnt; t++) {
            int j0 = __shfl_sync(0xffffffffu, myj, t);
            float4 v0 = *(const float4*)(V + (size_t)j0 * 128 + lane * 4);
            agg_step(u, b, v0, s, mx);
        }
    }
    float4 msg = make_float4(s.x * mx.x, s.y * mx.y, s.z * mx.z, s.w * mx.w);
    float* hp = g_hatom + (size_t)gw * 128 + lane * 4;
    float4 h = *(float4*)hp;
    if (!final_mode) {
        h.x *= msg.x; h.y *= msg.y; h.z *= msg.z; h.w *= msg.w;
        *(float4*)hp = h;
    } else {
        float4 o = make_float4(h.x * h.x * msg.x, h.y * h.y * msg.y,
                               h.z * h.z * msg.z, h.w * h.w * msg.w);
        *(float4*)(g_hbondN + (size_t)gw * 128 + lane * 4) = o;
    }
}

__global__ __launch_bounds__(256) void agg0_kernel(
    const float* __restrict__ eattr, const float* __restrict__ Wb,
    const float* __restrict__ bb, int n)
{
    __shared__ float Wbs[16][128];
    for (int i = threadIdx.x; i < 512; i += 256)
        ((float4*)Wbs)[i] = ((const float4*)Wb)[i];
    __syncthreads();
    int gw = (blockIdx.x * blockDim.x + threadIdx.x) >> 5;
    int lane = threadIdx.x & 31;
    if (gw >= n) return;
    int start = g_rowptr[gw], end = g_rowptr[gw + 1];
    float4 b = *(const float4*)(bb + lane * 4);
    float4 s  = make_float4(0.f, 0.f, 0.f, 0.f);
    float4 mx = make_float4(0.f, 0.f, 0.f, 0.f);
    for (int c = start; c < end; c += 32) {
        int cnt = end - c; if (cnt > 32) cnt = 32;
        int myE = g_sortedE[c + (lane < cnt ? lane : 0)];
        for (int t = 0; t < cnt; t++) {
            int eid = __shfl_sync(0xffffffffu, myE, t);
            const float4* ea = (const float4*)(eattr + (size_t)eid * 16);
            float ec[16];
            *(float4*)(&ec[0])  = ea[0];
            *(float4*)(&ec[4])  = ea[1];
            *(float4*)(&ec[8])  = ea[2];
            *(float4*)(&ec[12]) = ea[3];
            float4 m = b;
#pragma unroll
            for (int q = 0; q < 16; q++) {
                float4 w = *(const float4*)(&Wbs[q][lane * 4]);
                m.x = fmaf(ec[q], w.x, m.x);
                m.y = fmaf(ec[q], w.y, m.y);
                m.z = fmaf(ec[q], w.z, m.z);
                m.w = fmaf(ec[q], w.w, m.w);
            }
            m.x = fmaxf(m.x, 0.f); m.y = fmaxf(m.y, 0.f);
            m.z = fmaxf(m.z, 0.f); m.w = fmaxf(m.w, 0.f);
            s.x += m.x; s.y += m.y; s.z += m.z; s.w += m.w;
            mx.x = fmaxf(mx.x, m.x); mx.y = fmaxf(mx.y, m.y);
            mx.z = fmaxf(mx.z, m.z); mx.w = fmaxf(mx.w, m.w);
        }
    }
    float4 xp = *(const float4*)(g_xproj + (size_t)gw * 128 + lane * 4);
    float4 o = make_float4(xp.x * s.x * mx.x, xp.y * s.y * mx.y,
                           xp.z * s.z * mx.z, xp.w * s.w * mx.w);
    *(float4*)(g_hatom + (size_t)gw * 128 + lane * 4) = o;
}

__global__ __launch_bounds__(256) void bond0_kernel(
    const float* __restrict__ eattr, const float* __restrict__ Wb,
    const float* __restrict__ bb, int n)
{
    __shared__ float Wbs[16][128];
    for (int i = threadIdx.x; i < 512; i += 256)
        ((float4*)Wbs)[i] = ((const float4*)Wb)[i];
    __syncthreads();
    int v = (blockIdx.x * blockDim.x + threadIdx.x) >> 5;
    int lane = threadIdx.x & 31;
    if (v >= n) return;
    float4 m = *(const float4*)(bb + lane * 4);
    const float4* ea = (const float4*)(eattr + (size_t)v * 16);
    float ec[16];
    *(float4*)(&ec[0])  = ea[0];
    *(float4*)(&ec[4])  = ea[1];
    *(float4*)(&ec[8])  = ea[2];
    *(float4*)(&ec[12]) = ea[3];
#pragma unroll
    for (int q = 0; q < 16; q++) {
        float4 w = *(const float4*)(&Wbs[q][lane * 4]);
        m.x = fmaf(ec[q], w.x, m.x);
        m.y = fmaf(ec[q], w.y, m.y);
        m.z = fmaf(ec[q], w.z, m.z);
        m.w = fmaf(ec[q], w.w, m.w);
    }
    m.x = fmaxf(m.x, 0.f); m.y = fmaxf(m.y, 0.f);
    m.z = fmaxf(m.z, 0.f); m.w = fmaxf(m.w, 0.f);
    *(float4*)(g_hbondN + (size_t)v * 128 + lane * 4) = m;
}

// h_bondN[v] = relu(U[idxI[v]] - V[idxJ[v]] + b), v < N (edge ids 0..N-1).
__global__ __launch_bounds__(256) void bond_update_kernel(
    const float* __restrict__ V, const float* __restrict__ bias, int n)
{
    int v = (blockIdx.x * blockDim.x + threadIdx.x) >> 5;
    int lane = threadIdx.x & 31;
    if (v >= n) return;
    int i = g_idxI[v], j = g_idxJ[v];
    float4 u  = *(const float4*)(g_U + (size_t)i * 128 + lane * 4);
    float4 vv = *(const float4*)(V + (size_t)j * 128 + lane * 4);
    float4 b  = *(const float4*)(bias + lane * 4);
    float4 o = make_float4(fmaxf(u.x - vv.x + b.x, 0.f),
                           fmaxf(u.y - vv.y + b.y, 0.f),
                           fmaxf(u.z - vv.z + b.z, 0.f),
                           fmaxf(u.w - vv.w + b.w, 0.f));
    *(float4*)(g_hbondN + (size_t)v * 128 + lane * 4) = o;
}

// --------------------------------- launch -----------------------------------

extern "C" void kernel_launch(void* const* d_in, const int* in_sizes, int n_in,
                              void* d_out, int out_size) {
    const float* x      = (const float*)d_in[0];
    const int*   eraw   = (const int*)d_in[1];
    const float* eattr  = (const float*)d_in[2];
    const float* W_atom = (const float*)d_in[3];
    const float* b_atom = (const float*)d_in[4];
    const float* W_bond = (const float*)d_in[5];
    const float* b_bond = (const float*)d_in[6];
    const float* W_seq  = (const float*)d_in[7];
    const float* b_seq  = (const float*)d_in[8];
    const float* W_lin  = (const float*)d_in[9];
    const float* b_lin  = (const float*)d_in[10];
    float* out = (float*)d_out;

    int n = in_sizes[0] / 128;   // 30000
    int e = in_sizes[2] / 16;    // 480000
    if (n > NN_MAX) n = NN_MAX;
    if (e > EE_MAX) e = EE_MAX;

    float *p_xproj, *p_hatom, *p_hbondN, *p_U, *p_V, *p_V2;
    cudaGetSymbolAddress((void**)&p_xproj,  g_xproj);
    cudaGetSymbolAddress((void**)&p_hatom,  g_hatom);
    cudaGetSymbolAddress((void**)&p_hbondN, g_hbondN);
    cudaGetSymbolAddress((void**)&p_U,      g_U);
    cudaGetSymbolAddress((void**)&p_V,      g_V);
    cudaGetSymbolAddress((void**)&p_V2,     g_V2);

    static cudaStream_t s1 = 0;
    static cudaEvent_t evFork, evXP, evU0, evU1, evV0, evV1, evV2;
    static int inited = 0;
    if (!inited) {
        cudaFuncSetAttribute(gemm64_kernel,
                             cudaFuncAttributeMaxDynamicSharedMemorySize, G64_SMEM);
        cudaFuncSetAttribute(gemm_out_kernel,
                             cudaFuncAttributeMaxDynamicSharedMemorySize, GO_SMEM);
        cudaStreamCreateWithFlags(&s1, cudaStreamNonBlocking);
        cudaEventCreateWithFlags(&evFork, cudaEventDisableTiming);
        cudaEventCreateWithFlags(&evXP,   cudaEventDisableTiming);
        cudaEventCreateWithFlags(&evU0,   cudaEventDisableTiming);
        cudaEventCreateWithFlags(&evU1,   cudaEventDisableTiming);
        cudaEventCreateWithFlags(&evV0,   cudaEventDisableTiming);
        cudaEventCreateWithFlags(&evV1,   cudaEventDisableTiming);
        cudaEventCreateWithFlags(&evV2,   cudaEventDisableTiming);
        inited = 1;
    }
    cudaEvent_t evU[2] = {evU0, evU1};
    cudaEvent_t evV[3] = {evV0, evV1, evV2};
    float* Vbuf[3] = {p_V, p_V2, p_V};   // per-layer V buffer (ping-pong)

    int eb  = (e + 255) / 256;
    int nb  = (n + 255) / 256;
    int nwb = (n * 32 + 255) / 256;     // warp-per-node grids
    int g64 = (n + 63) / 64;            // BM=64 GEMM row blocks

    // Fork: side stream is independent of the CSR build.
    cudaEventRecord(evFork, 0);
    cudaStreamWaitEvent(s1, evFork, 0);

    // main: CSR build
    init_kernel<<<nb, 256>>>(eraw, e, n);
    convert_hist_kernel<<<eb, 256>>>(eraw, e);
    // side: x_proj = relu(x @ W_atom + b_atom)
    gemm64_kernel<<<g64, 128, G64_SMEM, s1>>>(x, x, W_atom, b_atom,
                                              p_xproj, p_xproj, n, g64, 1);
    cudaEventRecord(evXP, s1);
    scan_kernel<<<1, 1024>>>(n);
    scatter_kernel<<<eb, 256>>>(e);
    // side: h_bondN_0 = relu(edge_attr[0:n] @ W_bond + b_bond), then
    //       V_0 = h_bondN_0 @ W_0  (concurrent with agg0 on main)
    bond0_kernel<<<nwb, 256, 0, s1>>>(eattr, W_bond, b_bond, n);
    gemm64_kernel<<<g64, 128, G64_SMEM, s1>>>(p_hbondN, p_hbondN,
                                              W_seq, (const float*)0,
                                              Vbuf[0], Vbuf[0], n, g64, 0);
    cudaEventRecord(evV[0], s1);

    // main: agg0 needs CSR + xproj (NOT bond0)
    cudaStreamWaitEvent(0, evXP, 0);
    agg0_kernel<<<nwb, 256>>>(eattr, W_bond, b_bond, n);

    for (int l = 0; l < 3; l++) {
        const float* Wl = W_seq + (size_t)l * 128 * 128;
        const float* bl = b_seq + (size_t)l * 128;
        // main: U_l = h_atom @ W_l
        gemm64_kernel<<<g64, 128, G64_SMEM>>>(p_hatom, p_hatom, Wl,
                                              (const float*)0,
                                              p_U, p_U, n, g64, 0);
        if (l < 2) {
            // side: bond_update_l (needs U_l + V_l), then V_{l+1} GEMM —
            // both run concurrent with main's agg_l.
            cudaEventRecord(evU[l], 0);
            cudaStreamWaitEvent(s1, evU[l], 0);
            bond_update_kernel<<<nwb, 256, 0, s1>>>(Vbuf[l], bl, n);
            const float* Wn = W_seq + (size_t)(l + 1) * 128 * 128;
            gemm64_kernel<<<g64, 128, G64_SMEM, s1>>>(p_hbondN, p_hbondN, Wn,
                                                      (const float*)0,
                                                      Vbuf[l + 1], Vbuf[l + 1],
                                                      n, g64, 0);
            cudaEventRecord(evV[l + 1], s1);
        }
        // main: agg_l needs U_l (in-stream) + V_l (side)
        cudaStreamWaitEvent(0, evV[l], 0);
        agg_kernel<<<nwb, 256>>>(p_U, Vbuf[l], bl, n, (l == 2) ? 1 : 0);
    }

    // out = [hfin | x_proj] @ W_lin + b_lin
    gemm_out_kernel<<<g64, 128, GO_SMEM>>>(W_lin, b_lin, out, n);
}

// round 17
// speedup vs baseline: 1.1828x; 1.0007x over previous
#include <cuda_runtime.h>
#include <cstdint>

// ---------------------------------------------------------------------------
// CMPNN, restructured:
//   x_proj = relu(x @ W_atom + b)                         [N,128]
//   loop l=0..2:
//     msg[i] = sum_e m_e * max_e m_e ; h_atom *= msg
//     U = h_atom @ W_l ; V = h_bondN @ W_l                [N,128] each
//     h_bondN[v] = relu(U[iI[v]] - V[iJ[v]] + b_l)  (rows < N only)
//   final msg -> hfin = h_atom^2 * msg
//   out = [hfin | x_proj] @ W_lin + b_lin                 [N,64]
// GEMMs: scalar FFMA (R11 shape). Dual-stream schedule:
//   side stream: xproj, bond0, Vgemm_l, bond_update_l  (V double-buffered)
//   main stream: CSR build, agg0, Ugemm_l, agg_l, gemm_out
// CSR slimmed: detect-only init (globals start zeroed; scan re-zeros g_deg
// for graph replays), int4-coalesced register-resident scan (8 shuffle
// rounds/warp instead of 32), int2 loads in convert_hist.
// h_bond [E,128] is never materialized: m_e = relu(U[i_e]-V[j_e]+b).
// ---------------------------------------------------------------------------

#define NN_MAX 30000
#define EE_MAX 480000

__device__ int g_is64;
__device__ int g_idxI[EE_MAX];
__device__ int g_idxJ[EE_MAX];
__device__ __align__(16) int g_deg[NN_MAX + 8];      // zero at load; re-zeroed by scan
__device__ __align__(16) int g_rowptr[NN_MAX + 8];
__device__ __align__(16) int g_cursor[NN_MAX + 8];
__device__ int g_sortedJ[EE_MAX];
__device__ int g_sortedE[EE_MAX];

__device__ __align__(16) float g_xproj[NN_MAX * 128];
__device__ __align__(16) float g_hatom[NN_MAX * 128];
__device__ __align__(16) float g_hbondN[NN_MAX * 128];
__device__ __align__(16) float g_U[NN_MAX * 128];
__device__ __align__(16) float g_V[NN_MAX * 128];
__device__ __align__(16) float g_V2[NN_MAX * 128];

// ------------------------------- index setup -------------------------------

// int64-vs-int32 detect only (deg zeroing handled by module init + scan).
__global__ void detect_kernel(const int* __restrict__ raw, int e) {
    __shared__ int nz;
    if (threadIdx.x == 0) nz = 0;
    __syncthreads();
    int K = e < 2048 ? e : 2048;
    for (int t = threadIdx.x; t < K; t += blockDim.x)
        if (raw[2 * t + 1] != 0) nz = 1;
    __syncthreads();
    if (threadIdx.x == 0) g_is64 = (nz == 0) ? 1 : 0;
}

__global__ void convert_hist_kernel(const int* __restrict__ raw, int e) {
    int t = blockIdx.x * blockDim.x + threadIdx.x;
    if (t >= e) return;
    int i, j;
    if (g_is64) {
        const int2* r2 = (const int2*)raw;      // full-sector loads
        i = r2[t].x; j = r2[e + t].x;
    } else {
        i = raw[t]; j = raw[e + t];
    }
    g_idxI[t] = i;
    g_idxJ[t] = j;
    atomicAdd(&g_deg[i], 1);
}

// Single-block exclusive scan, int4-coalesced, register-resident.
// Warp w owns items [w*1024, w*1024+1024); round r (8 rounds): lane l holds
// the int4 at w*1024 + r*128 + l*4. Per round: 3 local adds + one 5-step
// warp shuffle scan (vs 32 serial scans before). Re-zeros g_deg as it reads.
__global__ __launch_bounds__(1024) void scan_kernel(int n) {
    __shared__ int wsum[32];
    int tid = threadIdx.x;
    int lane = tid & 31, w = tid >> 5;
    int base = w * 1024;                  // 32 warps * 1024 = 32768 >= NN_MAX
    int4 d[8];
    int preb[8];
    int running = 0;
#pragma unroll
    for (int r = 0; r < 8; r++) {
        int idx = base + r * 128 + lane * 4;
        int4 v = make_int4(0, 0, 0, 0);
        if (idx + 3 < n) {
            v = *(const int4*)(g_deg + idx);
            *(int4*)(g_deg + idx) = make_int4(0, 0, 0, 0);
        } else if (idx < n) {
            if (idx + 0 < n) { v.x = g_deg[idx + 0]; g_deg[idx + 0] = 0; }
            if (idx + 1 < n) { v.y = g_deg[idx + 1]; g_deg[idx + 1] = 0; }
            if (idx + 2 < n) { v.z = g_deg[idx + 2]; g_deg[idx + 2] = 0; }
        }
        d[r] = v;
        int tot4 = v.x + v.y + v.z + v.w;
        int incl = tot4;
#pragma unroll
        for (int o = 1; o < 32; o <<= 1) {
            int u = __shfl_up_sync(0xffffffffu, incl, o);
            if (lane >= o) incl += u;
        }
        preb[r] = running + incl - tot4;  // exclusive base for this int4
        running += __shfl_sync(0xffffffffu, incl, 31);
    }
    if (lane == 31) wsum[w] = running;
    __syncthreads();
    if (w == 0) {
        int v = wsum[lane];
#pragma unroll
        for (int o = 1; o < 32; o <<= 1) {
            int u = __shfl_up_sync(0xffffffffu, v, o);
            if (lane >= o) v += u;
        }
        wsum[lane] = v;                   // inclusive warp totals
    }
    __syncthreads();
    int off = (w > 0) ? wsum[w - 1] : 0;
#pragma unroll
    for (int r = 0; r < 8; r++) {
        int idx = base + r * 128 + lane * 4;
        if (idx >= n) continue;
        int p0 = off + preb[r];
        int p1 = p0 + d[r].x;
        int p2 = p1 + d[r].y;
        int p3 = p2 + d[r].z;
        if (idx + 3 < n) {
            int4 pv = make_int4(p0, p1, p2, p3);
            *(int4*)(g_rowptr + idx) = pv;
            *(int4*)(g_cursor + idx) = pv;
        } else {
            if (idx + 0 < n) { g_rowptr[idx + 0] = p0; g_cursor[idx + 0] = p0; }
            if (idx + 1 < n) { g_rowptr[idx + 1] = p1; g_cursor[idx + 1] = p1; }
            if (idx + 2 < n) { g_rowptr[idx + 2] = p2; g_cursor[idx + 2] = p2; }
        }
    }
    if (tid == 1023) g_rowptr[n] = wsum[31];
}

__global__ void scatter_kernel(int e) {
    int t = blockIdx.x * blockDim.x + threadIdx.x;
    if (t >= e) return;
    int i = g_idxI[t];
    int p = atomicAdd(&g_cursor[i], 1);
    g_sortedJ[p] = g_idxJ[t];
    g_sortedE[p] = t;
}

// ------------------------------ 64-row SGEMM --------------------------------
// C[M,128] = act(A[M,128] @ W[128,128] + bias), BM=64 per CTA, 128 threads.
// Dual-source: blocks < nblk use (A1,C1), the rest (A2,C2).
// cp.async 2-stage pipeline over BK=32 chunks; conflict-free swizzled A.

#define G64_STG_A (64 * 32)                 // floats
#define G64_STG_B (32 * 128)                // floats
#define G64_STG   (G64_STG_A + G64_STG_B)   // 6144 floats = 24 KB
#define G64_SMEM  (2 * G64_STG * 4)         // 48 KB

__device__ __forceinline__ uint32_t smem_u32(const void* p) {
    uint32_t a;
    asm("{ .reg .u64 t; cvta.to.shared.u64 t, %1; cvt.u32.u64 %0, t; }"
        : "=r"(a) : "l"(p));
    return a;
}
__device__ __forceinline__ void cp16(uint32_t dst, const void* src) {
    asm volatile("cp.async.ca.shared.global [%0], [%1], 16;"
                 :: "r"(dst), "l"(src));
}

__global__ __launch_bounds__(128) void gemm64_kernel(
    const float* __restrict__ A1, const float* __restrict__ A2,
    const float* __restrict__ W, const float* __restrict__ bias,
    float* __restrict__ C1, float* __restrict__ C2,
    int M, int nblk, int act)
{
    extern __shared__ float sm[];
    uint32_t sbase = smem_u32(sm);

    const float* __restrict__ A;
    float* __restrict__ C;
    int bx = blockIdx.x;
    if (bx < nblk) { A = A1; C = C1; } else { A = A2; C = C2; bx -= nblk; }
    int row0 = bx * 64;
    int tid = threadIdx.x;
    int tx = tid & 15, ty = tid >> 4;

    auto load_chunk = [&](int c, int s) {
        uint32_t aBase = sbase + (uint32_t)(s * G64_STG) * 4u;
        uint32_t bBase = aBase + (uint32_t)G64_STG_A * 4u;
#pragma unroll
        for (int i = 0; i < 4; i++) {           // A: 64x32 fl = 512 f4
            int idx = tid + i * 128;
            int r = idx >> 3, q = idx & 7;
            int gr = row0 + r; if (gr > M - 1) gr = M - 1;   // tail rows discarded
            uint32_t dst = aBase + (uint32_t)(r * 32 + ((q ^ (r & 7)) << 2)) * 4u;
            cp16(dst, A + (size_t)gr * 128 + c * 32 + q * 4);
        }
#pragma unroll
        for (int i = 0; i < 8; i++) {           // B: 32x128 fl = 1024 f4
            int idx = tid + i * 128;
            int k = idx >> 5, q = idx & 31;
            uint32_t dst = bBase + (uint32_t)(k * 128 + q * 4) * 4u;
            cp16(dst, W + (size_t)(c * 32 + k) * 128 + q * 4);
        }
        asm volatile("cp.async.commit_group;");
    };

    float acc[8][8];
#pragma unroll
    for (int i = 0; i < 8; i++)
#pragma unroll
        for (int j = 0; j < 8; j++) acc[i][j] = 0.f;

    load_chunk(0, 0);

    for (int c = 0; c < 4; c++) {
        int s = c & 1;
        if (c < 3) {
            load_chunk(c + 1, s ^ 1);
            asm volatile("cp.async.wait_group 1;");
        } else {
            asm volatile("cp.async.wait_group 0;");
        }
        __syncthreads();
        const float* Asf = sm + s * G64_STG;
        const float* Bsf = Asf + G64_STG_A;
#pragma unroll 2
        for (int kq = 0; kq < 8; kq++) {        // k-quad: 4 k-steps
            float4 a4[8];
#pragma unroll
            for (int i = 0; i < 8; i++)
                a4[i] = *(const float4*)(Asf + (ty * 8 + i) * 32 + ((kq ^ i) << 2));
#pragma unroll
            for (int kk = 0; kk < 4; kk++) {
                int k = kq * 4 + kk;
                float4 b0 = *(const float4*)(Bsf + k * 128 + 4 * tx);
                float4 b1 = *(const float4*)(Bsf + k * 128 + 64 + 4 * tx);
                float a[8];
#pragma unroll
                for (int i = 0; i < 8; i++)
                    a[i] = (kk == 0) ? a4[i].x : (kk == 1) ? a4[i].y
                         : (kk == 2) ? a4[i].z : a4[i].w;
#pragma unroll
                for (int i = 0; i < 8; i++) {
                    acc[i][0] = fmaf(a[i], b0.x, acc[i][0]);
                    acc[i][1] = fmaf(a[i], b0.y, acc[i][1]);
                    acc[i][2] = fmaf(a[i], b0.z, acc[i][2]);
                    acc[i][3] = fmaf(a[i], b0.w, acc[i][3]);
                    acc[i][4] = fmaf(a[i], b1.x, acc[i][4]);
                    acc[i][5] = fmaf(a[i], b1.y, acc[i][5]);
                    acc[i][6] = fmaf(a[i], b1.z, acc[i][6]);
                    acc[i][7] = fmaf(a[i], b1.w, acc[i][7]);
                }
            }
        }
        __syncthreads();
    }

    float bb[8];
    if (bias) {
#pragma unroll
        for (int j = 0; j < 4; j++) { bb[j] = bias[4 * tx + j]; bb[4 + j] = bias[64 + 4 * tx + j]; }
    } else {
#pragma unroll
        for (int j = 0; j < 8; j++) bb[j] = 0.f;
    }
#pragma unroll
    for (int i = 0; i < 8; i++) {
        int r = row0 + ty * 8 + i;
        if (r < M) {
            float v[8];
#pragma unroll
            for (int j = 0; j < 8; j++) {
                float t = acc[i][j] + bb[j];
                v[j] = act ? fmaxf(t, 0.f) : t;
            }
            float* op = C + (size_t)r * 128;
            *(float4*)(op + 4 * tx)      = make_float4(v[0], v[1], v[2], v[3]);
            *(float4*)(op + 64 + 4 * tx) = make_float4(v[4], v[5], v[6], v[7]);
        }
    }
}

// -------------------------- out GEMM (BM=64, N=64) ---------------------------
// out[N,64] = [hfin | xproj] @ W_lin[256,64] + b_lin. K=256 in 8 chunks;
// chunks 0-3 read g_hbondN (hfin), 4-7 g_xproj. 128 threads, 8x4 acc.

#define GO_STG_A (64 * 32)
#define GO_STG_B (32 * 64)
#define GO_STG   (GO_STG_A + GO_STG_B)      // 4096 floats = 16 KB
#define GO_SMEM  (2 * GO_STG * 4)           // 32 KB

__global__ __launch_bounds__(128) void gemm_out_kernel(
    const float* __restrict__ Wlin, const float* __restrict__ blin,
    float* __restrict__ out, int M)
{
    extern __shared__ float sm[];
    uint32_t sbase = smem_u32(sm);
    int row0 = blockIdx.x * 64;
    int tid = threadIdx.x;
    int tx = tid & 15, ty = tid >> 4;

    auto load_chunk = [&](int c, int s) {
        const float* Asrc = (c < 4) ? g_hbondN : g_xproj;
        int kb = (c & 3) * 32;
        uint32_t aBase = sbase + (uint32_t)(s * GO_STG) * 4u;
        uint32_t bBase = aBase + (uint32_t)GO_STG_A * 4u;
#pragma unroll
        for (int i = 0; i < 4; i++) {           // A: 64x32 fl = 512 f4
            int idx = tid + i * 128;
            int r = idx >> 3, q = idx & 7;
            int gr = row0 + r; if (gr > M - 1) gr = M - 1;
            uint32_t dst = aBase + (uint32_t)(r * 32 + ((q ^ (r & 7)) << 2)) * 4u;
            cp16(dst, Asrc + (size_t)gr * 128 + kb + q * 4);
        }
#pragma unroll
        for (int i = 0; i < 4; i++) {           // B: 32x64 fl = 512 f4
            int idx = tid + i * 128;
            int k = idx >> 4, q = idx & 15;
            uint32_t dst = bBase + (uint32_t)(k * 64 + q * 4) * 4u;
            cp16(dst, Wlin + (size_t)(c * 32 + k) * 64 + q * 4);
        }
        asm volatile("cp.async.commit_group;");
    };

    float acc[8][4];
#pragma unroll
    for (int i = 0; i < 8; i++)
#pragma unroll
        for (int j = 0; j < 4; j++) acc[i][j] = 0.f;

    load_chunk(0, 0);

    for (int c = 0; c < 8; c++) {
        int s = c & 1;
        if (c < 7) {
            load_chunk(c + 1, s ^ 1);
            asm volatile("cp.async.wait_group 1;");
        } else {
            asm volatile("cp.async.wait_group 0;");
        }
        __syncthreads();
        const float* Asf = sm + s * GO_STG;
        const float* Bsf = Asf + GO_STG_A;
#pragma unroll 2
        for (int kq = 0; kq < 8; kq++) {
            float4 a4[8];
#pragma unroll
            for (int i = 0; i < 8; i++) {
                int r = ty * 8 + i;
                a4[i] = *(const float4*)(Asf + r * 32 + ((kq ^ (r & 7)) << 2));
            }
#pragma unroll
            for (int kk = 0; kk < 4; kk++) {
                int k = kq * 4 + kk;
                float4 b0 = *(const float4*)(Bsf + k * 64 + 4 * tx);
                float a[8];
#pragma unroll
                for (int i = 0; i < 8; i++)
                    a[i] = (kk == 0) ? a4[i].x : (kk == 1) ? a4[i].y
                         : (kk == 2) ? a4[i].z : a4[i].w;
#pragma unroll
                for (int i = 0; i < 8; i++) {
                    acc[i][0] = fmaf(a[i], b0.x, acc[i][0]);
                    acc[i][1] = fmaf(a[i], b0.y, acc[i][1]);
                    acc[i][2] = fmaf(a[i], b0.z, acc[i][2]);
                    acc[i][3] = fmaf(a[i], b0.w, acc[i][3]);
                }
            }
        }
        __syncthreads();
    }

    float bb[4] = {blin[4 * tx], blin[4 * tx + 1], blin[4 * tx + 2], blin[4 * tx + 3]};
#pragma unroll
    for (int i = 0; i < 8; i++) {
        int r = row0 + ty * 8 + i;
        if (r < M) {
            *(float4*)(out + (size_t)r * 64 + 4 * tx) =
                make_float4(acc[i][0] + bb[0], acc[i][1] + bb[1],
                            acc[i][2] + bb[2], acc[i][3] + bb[3]);
        }
    }
}

// ------------------------- per-edge helpers / agg ---------------------------

__device__ __forceinline__ void agg_step(const float4& u, const float4& b,
                                         const float4& v, float4& s, float4& mx) {
    float m0 = fmaxf(u.x - v.x + b.x, 0.f);
    float m1 = fmaxf(u.y - v.y + b.y, 0.f);
    float m2 = fmaxf(u.z - v.z + b.z, 0.f);
    float m3 = fmaxf(u.w - v.w + b.w, 0.f);
    s.x += m0; s.y += m1; s.z += m2; s.w += m3;
    mx.x = fmaxf(mx.x, m0); mx.y = fmaxf(mx.y, m1);
    mx.z = fmaxf(mx.z, m2); mx.w = fmaxf(mx.w, m3);
}

__global__ __launch_bounds__(256) void agg_kernel(
    const float* __restrict__ U, const float* __restrict__ V,
    const float* __restrict__ bias, int n, int final_mode)
{
    int gw = (blockIdx.x * blockDim.x + threadIdx.x) >> 5;
    int lane = threadIdx.x & 31;
    if (gw >= n) return;
    int start = g_rowptr[gw], end = g_rowptr[gw + 1];
    float4 u = *(const float4*)(U + (size_t)gw * 128 + lane * 4);
    float4 b = *(const float4*)(bias + lane * 4);
    float4 s  = make_float4(0.f, 0.f, 0.f, 0.f);
    float4 mx = make_float4(0.f, 0.f, 0.f, 0.f);
    for (int c = start; c < end; c += 32) {
        int cnt = end - c; if (cnt > 32) cnt = 32;
        int myj = g_sortedJ[c + (lane < cnt ? lane : 0)];
        int t = 0;
        for (; t + 4 <= cnt; t += 4) {
            int j0 = __shfl_sync(0xffffffffu, myj, t);
            int j1 = __shfl_sync(0xffffffffu, myj, t + 1);
            int j2 = __shfl_sync(0xffffffffu, myj, t + 2);
            int j3 = __shfl_sync(0xffffffffu, myj, t + 3);
            float4 v0 = *(const float4*)(V + (size_t)j0 * 128 + lane * 4);
            float4 v1 = *(const float4*)(V + (size_t)j1 * 128 + lane * 4);
            float4 v2 = *(const float4*)(V + (size_t)j2 * 128 + lane * 4);
            float4 v3 = *(const float4*)(V + (size_t)j3 * 128 + lane * 4);
            agg_step(u, b, v0, s, mx);
            agg_step(u, b, v1, s, mx);
            agg_step(u, b, v2, s, mx);
            agg_step(u, b, v3, s, mx);
        }
        for (; t < cnt; t++) {
            int j0 = __shfl_sync(0xffffffffu, myj, t);
            float4 v0 = *(const float4*)(V + (size_t)j0 * 128 + lane * 4);
            agg_step(u, b, v0, s, mx);
        }
    }
    float4 msg = make_float4(s.x * mx.x, s.y * mx.y, s.z * mx.z, s.w * mx.w);
    float* hp = g_hatom + (size_t)gw * 128 + lane * 4;
    float4 h = *(float4*)hp;
    if (!final_mode) {
        h.x *= msg.x; h.y *= msg.y; h.z *= msg.z; h.w *= msg.w;
        *(float4*)hp = h;
    } else {
        float4 o = make_float4(h.x * h.x * msg.x, h.y * h.y * msg.y,
                               h.z * h.z * msg.z, h.w * h.w * msg.w);
        *(float4*)(g_hbondN + (size_t)gw * 128 + lane * 4) = o;
    }
}

__global__ __launch_bounds__(256) void agg0_kernel(
    const float* __restrict__ eattr, const float* __restrict__ Wb,
    const float* __restrict__ bb, int n)
{
    __shared__ float Wbs[16][128];
    for (int i = threadIdx.x; i < 512; i += 256)
        ((float4*)Wbs)[i] = ((const float4*)Wb)[i];
    __syncthreads();
    int gw = (blockIdx.x * blockDim.x + threadIdx.x) >> 5;
    int lane = threadIdx.x & 31;
    if (gw >= n) return;
    int start = g_rowptr[gw], end = g_rowptr[gw + 1];
    float4 b = *(const float4*)(bb + lane * 4);
    float4 s  = make_float4(0.f, 0.f, 0.f, 0.f);
    float4 mx = make_float4(0.f, 0.f, 0.f, 0.f);
    for (int c = start; c < end; c += 32) {
        int cnt = end - c; if (cnt > 32) cnt = 32;
        int myE = g_sortedE[c + (lane < cnt ? lane : 0)];
        for (int t = 0; t < cnt; t++) {
            int eid = __shfl_sync(0xffffffffu, myE, t);
            const float4* ea = (const float4*)(eattr + (size_t)eid * 16);
            float ec[16];
            *(float4*)(&ec[0])  = ea[0];
            *(float4*)(&ec[4])  = ea[1];
            *(float4*)(&ec[8])  = ea[2];
            *(float4*)(&ec[12]) = ea[3];
            float4 m = b;
#pragma unroll
            for (int q = 0; q < 16; q++) {
                float4 w = *(const float4*)(&Wbs[q][lane * 4]);
                m.x = fmaf(ec[q], w.x, m.x);
                m.y = fmaf(ec[q], w.y, m.y);
                m.z = fmaf(ec[q], w.z, m.z);
                m.w = fmaf(ec[q], w.w, m.w);
            }
            m.x = fmaxf(m.x, 0.f); m.y = fmaxf(m.y, 0.f);
            m.z = fmaxf(m.z, 0.f); m.w = fmaxf(m.w, 0.f);
            s.x += m.x; s.y += m.y; s.z += m.z; s.w += m.w;
            mx.x = fmaxf(mx.x, m.x); mx.y = fmaxf(mx.y, m.y);
            mx.z = fmaxf(mx.z, m.z); mx.w = fmaxf(mx.w, m.w);
        }
    }
    float4 xp = *(const float4*)(g_xproj + (size_t)gw * 128 + lane * 4);
    float4 o = make_float4(xp.x * s.x * mx.x, xp.y * s.y * mx.y,
                           xp.z * s.z * mx.z, xp.w * s.w * mx.w);
    *(float4*)(g_hatom + (size_t)gw * 128 + lane * 4) = o;
}

__global__ __launch_bounds__(256) void bond0_kernel(
    const float* __restrict__ eattr, const float* __restrict__ Wb,
    const float* __restrict__ bb, int n)
{
    __shared__ float Wbs[16][128];
    for (int i = threadIdx.x; i < 512; i += 256)
        ((float4*)Wbs)[i] = ((const float4*)Wb)[i];
    __syncthreads();
    int v = (blockIdx.x * blockDim.x + threadIdx.x) >> 5;
    int lane = threadIdx.x & 31;
    if (v >= n) return;
    float4 m = *(const float4*)(bb + lane * 4);
    const float4* ea = (const float4*)(eattr + (size_t)v * 16);
    float ec[16];
    *(float4*)(&ec[0])  = ea[0];
    *(float4*)(&ec[4])  = ea[1];
    *(float4*)(&ec[8])  = ea[2];
    *(float4*)(&ec[12]) = ea[3];
#pragma unroll
    for (int q = 0; q < 16; q++) {
        float4 w = *(const float4*)(&Wbs[q][lane * 4]);
        m.x = fmaf(ec[q], w.x, m.x);
        m.y = fmaf(ec[q], w.y, m.y);
        m.z = fmaf(ec[q], w.z, m.z);
        m.w = fmaf(ec[q], w.w, m.w);
    }
    m.x = fmaxf(m.x, 0.f); m.y = fmaxf(m.y, 0.f);
    m.z = fmaxf(m.z, 0.f); m.w = fmaxf(m.w, 0.f);
    *(float4*)(g_hbondN + (size_t)v * 128 + lane * 4) = m;
}

// h_bondN[v] = relu(U[idxI[v]] - V[idxJ[v]] + b), v < N (edge ids 0..N-1).
__global__ __launch_bounds__(256) void bond_update_kernel(
    const float* __restrict__ V, const float* __restrict__ bias, int n)
{
    int v = (blockIdx.x * blockDim.x + threadIdx.x) >> 5;
    int lane = threadIdx.x & 31;
    if (v >= n) return;
    int i = g_idxI[v], j = g_idxJ[v];
    float4 u  = *(const float4*)(g_U + (size_t)i * 128 + lane * 4);
    float4 vv = *(const float4*)(V + (size_t)j * 128 + lane * 4);
    float4 b  = *(const float4*)(bias + lane * 4);
    float4 o = make_float4(fmaxf(u.x - vv.x + b.x, 0.f),
                           fmaxf(u.y - vv.y + b.y, 0.f),
                           fmaxf(u.z - vv.z + b.z, 0.f),
                           fmaxf(u.w - vv.w + b.w, 0.f));
    *(float4*)(g_hbondN + (size_t)v * 128 + lane * 4) = o;
}

// --------------------------------- launch -----------------------------------

extern "C" void kernel_launch(void* const* d_in, const int* in_sizes, int n_in,
                              void* d_out, int out_size) {
    const float* x      = (const float*)d_in[0];
    const int*   eraw   = (const int*)d_in[1];
    const float* eattr  = (const float*)d_in[2];
    const float* W_atom = (const float*)d_in[3];
    const float* b_atom = (const float*)d_in[4];
    const float* W_bond = (const float*)d_in[5];
    const float* b_bond = (const float*)d_in[6];
    const float* W_seq  = (const float*)d_in[7];
    const float* b_seq  = (const float*)d_in[8];
    const float* W_lin  = (const float*)d_in[9];
    const float* b_lin  = (const float*)d_in[10];
    float* out = (float*)d_out;

    int n = in_sizes[0] / 128;   // 30000
    int e = in_sizes[2] / 16;    // 480000
    if (n > NN_MAX) n = NN_MAX;
    if (e > EE_MAX) e = EE_MAX;

    float *p_xproj, *p_hatom, *p_hbondN, *p_U, *p_V, *p_V2;
    cudaGetSymbolAddress((void**)&p_xproj,  g_xproj);
    cudaGetSymbolAddress((void**)&p_hatom,  g_hatom);
    cudaGetSymbolAddress((void**)&p_hbondN, g_hbondN);
    cudaGetSymbolAddress((void**)&p_U,      g_U);
    cudaGetSymbolAddress((void**)&p_V,      g_V);
    cudaGetSymbolAddress((void**)&p_V2,     g_V2);

    static cudaStream_t s1 = 0;
    static cudaEvent_t evFork, evXP, evU0, evU1, evV0, evV1, evV2;
    static int inited = 0;
    if (!inited) {
        cudaFuncSetAttribute(gemm64_kernel,
                             cudaFuncAttributeMaxDynamicSharedMemorySize, G64_SMEM);
        cudaFuncSetAttribute(gemm_out_kernel,
                             cudaFuncAttributeMaxDynamicSharedMemorySize, GO_SMEM);
        cudaStreamCreateWithFlags(&s1, cudaStreamNonBlocking);
        cudaEventCreateWithFlags(&evFork, cudaEventDisableTiming);
        cudaEventCreateWithFlags(&evXP,   cudaEventDisableTiming);
        cudaEventCreateWithFlags(&evU0,   cudaEventDisableTiming);
        cudaEventCreateWithFlags(&evU1,   cudaEventDisableTiming);
        cudaEventCreateWithFlags(&evV0,   cudaEventDisableTiming);
        cudaEventCreateWithFlags(&evV1,   cudaEventDisableTiming);
        cudaEventCreateWithFlags(&evV2,   cudaEventDisableTiming);
        inited = 1;
    }
    cudaEvent_t evU[2] = {evU0, evU1};
    cudaEvent_t evV[3] = {evV0, evV1, evV2};
    float* Vbuf[3] = {p_V, p_V2, p_V};   // per-layer V buffer (ping-pong)

    int eb  = (e + 255) / 256;
    int nwb = (n * 32 + 255) / 256;     // warp-per-node grids
    int g64 = (n + 63) / 64;            // BM=64 GEMM row blocks

    // Fork: side stream is independent of the CSR build.
    cudaEventRecord(evFork, 0);
    cudaStreamWaitEvent(s1, evFork, 0);

    // main: CSR build (g_deg is zeroed: module init on first run, scan on
    // subsequent replays)
    detect_kernel<<<1, 256>>>(eraw, e);
    convert_hist_kernel<<<eb, 256>>>(eraw, e);
    // side: x_proj = relu(x @ W_atom + b_atom)
    gemm64_kernel<<<g64, 128, G64_SMEM, s1>>>(x, x, W_atom, b_atom,
                                              p_xproj, p_xproj, n, g64, 1);
    cudaEventRecord(evXP, s1);
    scan_kernel<<<1, 1024>>>(n);
    scatter_kernel<<<eb, 256>>>(e);
    // side: h_bondN_0 = relu(edge_attr[0:n] @ W_bond + b_bond), then
    //       V_0 = h_bondN_0 @ W_0  (concurrent with agg0 on main)
    bond0_kernel<<<nwb, 256, 0, s1>>>(eattr, W_bond, b_bond, n);
    gemm64_kernel<<<g64, 128, G64_SMEM, s1>>>(p_hbondN, p_hbondN,
                                              W_seq, (const float*)0,
                                              Vbuf[0], Vbuf[0], n, g64, 0);
    cudaEventRecord(evV[0], s1);

    // main: agg0 needs CSR + xproj (NOT bond0)
    cudaStreamWaitEvent(0, evXP, 0);
    agg0_kernel<<<nwb, 256>>>(eattr, W_bond, b_bond, n);

    for (int l = 0; l < 3; l++) {
        const float* Wl = W_seq + (size_t)l * 128 * 128;
        const float* bl = b_seq + (size_t)l * 128;
        // main: U_l = h_atom @ W_l
        gemm64_kernel<<<g64, 128, G64_SMEM>>>(p_hatom, p_hatom, Wl,
                                              (const float*)0,
                                              p_U, p_U, n, g64, 0);
        if (l < 2) {
            // side: bond_update_l (needs U_l + V_l), then V_{l+1} GEMM —
            // both run concurrent with main's agg_l.
            cudaEventRecord(evU[l], 0);
            cudaStreamWaitEvent(s1, evU[l], 0);
            bond_update_kernel<<<nwb, 256, 0, s1>>>(Vbuf[l], bl, n);
            const float* Wn = W_seq + (size_t)(l + 1) * 128 * 128;
            gemm64_kernel<<<g64, 128, G64_SMEM, s1>>>(p_hbondN, p_hbondN, Wn,
                                                      (const float*)0,
                                                      Vbuf[l + 1], Vbuf[l + 1],
                                                      n, g64, 0);
            cudaEventRecord(evV[l + 1], s1);
        }
        // main: agg_l needs U_l (in-stream) + V_l (side)
        cudaStreamWaitEvent(0, evV[l], 0);
        agg_kernel<<<nwb, 256>>>(p_U, Vbuf[l], bl, n, (l == 2) ? 1 : 0);
    }

    // out = [hfin | x_proj] @ W_lin + b_lin
    gemm_out_kernel<<<g64, 128, GO_SMEM>>>(W_lin, b_lin, out, n);
}